// round 1
// baseline (speedup 1.0000x reference)
#include <cuda_runtime.h>
#include <stdint.h>

#define B_ 4
#define T_ 1024
#define NX_ 1024
#define H_ 16
#define D_ 64
#define KMAX_ 32
#define NLOC_ 64

// ---------------- scratch (device globals: no runtime allocation) ----------------
__device__ float g_q[B_*H_*T_*D_];          // [b,h,t,d]
__device__ float g_k[B_*H_*T_*D_];
__device__ float g_v[B_*H_*T_*D_];
__device__ float g_lr2[B_*H_*NLOC_*T_];     // [b,h,n,s]
__device__ float g_att[B_*T_*NX_];          // [b,t,h*D+d]  (pre-proj attention out)

// ---------------- Kernel 1: QKV GEMM + scatter ----------------
// C[m,n] = sum_k X[m,k]*W[k,n] + bias[n];  M=4096, K=1024, N=3072
__global__ __launch_bounds__(256) void qkv_gemm(
    const float* __restrict__ X, const float* __restrict__ W,
    const float* __restrict__ bias)
{
    __shared__ float As[8][128];
    __shared__ float Bs[8][128];
    const int n0 = blockIdx.x * 128;
    const int m0 = blockIdx.y * 128;
    const int tid = threadIdx.x;
    const int tx = tid & 15, ty = tid >> 4;
    const int arow = tid >> 1, acol = (tid & 1) * 4;
    const int brow = tid >> 5, bcol = (tid & 31) * 4;

    float acc[8][8];
    #pragma unroll
    for (int i = 0; i < 8; i++)
        #pragma unroll
        for (int j = 0; j < 8; j++) acc[i][j] = 0.0f;

    for (int k0 = 0; k0 < 1024; k0 += 8) {
        float4 a = *(const float4*)(X + (size_t)(m0 + arow) * 1024 + k0 + acol);
        As[acol + 0][arow] = a.x; As[acol + 1][arow] = a.y;
        As[acol + 2][arow] = a.z; As[acol + 3][arow] = a.w;
        float4 b4 = *(const float4*)(W + (size_t)(k0 + brow) * 3072 + n0 + bcol);
        *(float4*)(&Bs[brow][bcol]) = b4;
        __syncthreads();
        #pragma unroll
        for (int kk = 0; kk < 8; kk++) {
            float ar[8], br[8];
            #pragma unroll
            for (int i = 0; i < 8; i++) ar[i] = As[kk][ty * 8 + i];
            #pragma unroll
            for (int j = 0; j < 8; j++) br[j] = Bs[kk][tx * 8 + j];
            #pragma unroll
            for (int i = 0; i < 8; i++)
                #pragma unroll
                for (int j = 0; j < 8; j++) acc[i][j] += ar[i] * br[j];
        }
        __syncthreads();
    }
    #pragma unroll
    for (int i = 0; i < 8; i++) {
        int m = m0 + ty * 8 + i;
        int b = m >> 10, t = m & 1023;
        #pragma unroll
        for (int j = 0; j < 8; j++) {
            int n = n0 + tx * 8 + j;
            float val = acc[i][j] + bias[n];
            int which = n >> 10;               // 0=q 1=k 2=v
            int c = n & 1023;
            int h = c >> 6, d = c & 63;
            float* dst = (which == 0) ? g_q : (which == 1) ? g_k : g_v;
            dst[(size_t)(((b * H_) + h) * T_ + t) * D_ + d] = val;
        }
    }
}

// ---------------- Kernel 2: lr2[b,h,n,s] = (LR_Q[h,n,:] . k[b,h,s,:]) / 8 ----------------
__global__ __launch_bounds__(256) void lr2_kernel(const float* __restrict__ LR_Q)
{
    __shared__ float LQ[64][64];
    __shared__ float Ks[64][65];
    const int bh = blockIdx.y;
    const int h = bh & (H_ - 1);
    const int s0 = blockIdx.x * 64;
    const int tid = threadIdx.x;

    for (int it = 0; it < 16; it++) {
        int f = it * 256 + tid;
        LQ[f >> 6][f & 63] = LR_Q[(size_t)(h * 64 + (f >> 6)) * 64 + (f & 63)];
    }
    for (int it = 0; it < 16; it++) {
        int f = it * 256 + tid;
        Ks[f >> 6][f & 63] = g_k[(size_t)(bh * T_ + s0 + (f >> 6)) * 64 + (f & 63)];
    }
    __syncthreads();

    const int s = tid & 63;
    const int g = tid >> 6;       // 0..3 -> 16 n each
    float acc[16];
    #pragma unroll
    for (int nn = 0; nn < 16; nn++) acc[nn] = 0.0f;
    for (int d = 0; d < 64; d++) {
        float kv = Ks[s][d];
        #pragma unroll
        for (int nn = 0; nn < 16; nn++) acc[nn] += LQ[g * 16 + nn][d] * kv;
    }
    #pragma unroll
    for (int nn = 0; nn < 16; nn++)
        g_lr2[(size_t)(bh * 64 + g * 16 + nn) * T_ + s0 + s] = acc[nn] * 0.125f;
}

// ---------------- Kernel 3: fused causal attention with all bias terms ----------------
struct AttSmem {
    float q[32][64];       // query tile
    float qr[32][33];      // q . rel_k_emb[id], causal ids 0..32 only
    float lr1[32][64];     // (q . LR_K[h,n]) / 8
    float rv[33][64];      // rel_v_emb rows 0..32
    float kT[64][33];      // key chunk, transposed [d][s]
    float v[32][65];       // value chunk [s][d]
    float lr2s[64][33];    // lr2 chunk [n][s]
    float relw[64];        // rel_w_emb[:, h]
};

__global__ __launch_bounds__(128) void attn_kernel(
    const int* __restrict__ rel, const float* __restrict__ tds,
    const float* __restrict__ LR_K, const int* __restrict__ LR_map,
    const float* __restrict__ rel_w_emb, const float* __restrict__ rel_k_emb,
    const float* __restrict__ rel_v_emb)
{
    extern __shared__ char smem_raw[];
    AttSmem& sm = *reinterpret_cast<AttSmem*>(smem_raw);

    const int t0 = blockIdx.x * 32;
    const int bh = blockIdx.y;
    const int b = bh >> 4, h = bh & 15;
    const int tid = threadIdx.x;
    const int lane = tid & 31, w = tid >> 5;
    const float inv_sqrt_d = 0.125f;
    const float inv_sqrt2 = 0.70710678f;

    const float* qbase = g_q + (size_t)bh * T_ * D_;
    const float* kbase = g_k + (size_t)bh * T_ * D_;
    const float* vbase = g_v + (size_t)bh * T_ * D_;
    const float* lr2base = g_lr2 + (size_t)bh * NLOC_ * T_;
    const int* relbase = rel + (size_t)b * T_ * T_;
    const int* lmbase = LR_map + (size_t)b * T_ * T_;
    const float* tdsbase = tds + (size_t)bh * T_ * T_;

    // ---- prologue loads ----
    for (int f = tid; f < 32 * 64; f += 128)
        sm.q[f >> 6][f & 63] = qbase[(size_t)t0 * 64 + f];
    if (tid < 64) sm.relw[tid] = rel_w_emb[tid * H_ + h];
    for (int f = tid; f < 33 * 64; f += 128)
        sm.rv[f >> 6][f & 63] = rel_v_emb[f];
    __syncthreads();

    // qr[r][id] = q[r] . rel_k_emb[id]
    for (int task = tid; task < 32 * 33; task += 128) {
        int r = task / 33, id = task % 33;
        const float* rk = rel_k_emb + id * 64;
        float a = 0.0f;
        #pragma unroll 16
        for (int d = 0; d < 64; d++) a += sm.q[r][d] * rk[d];
        sm.qr[r][id] = a;
    }
    // lr1[r][n] = (q[r] . LR_K[h,n]) / 8
    for (int task = tid; task < 32 * 64; task += 128) {
        int r = task >> 6, n = task & 63;
        const float* lk = LR_K + (size_t)(h * 64 + n) * 64;
        float a = 0.0f;
        #pragma unroll 16
        for (int d = 0; d < 64; d++) a += sm.q[r][d] * lk[d];
        sm.lr1[r][n] = a * inv_sqrt_d;
    }

    // per-row online-softmax state: warp w owns local rows w*8..w*8+7
    float m_[8], l_[8], acc0[8], acc1[8];
    #pragma unroll
    for (int rr = 0; rr < 8; rr++) {
        m_[rr] = -1e30f; l_[rr] = 0.0f; acc0[rr] = 0.0f; acc1[rr] = 0.0f;
    }

    const int nchunk = blockIdx.x + 1;       // causal: keys up to t0+31
    for (int c = 0; c < nchunk; c++) {
        const int s0 = c * 32;
        __syncthreads();
        // load k (transposed), v
        for (int f = tid; f < 2048; f += 128) {
            int s = f >> 6, d = f & 63;
            float kv = kbase[(size_t)(s0 + s) * 64 + d];
            sm.kT[d][s] = kv;
            sm.v[s][d] = vbase[(size_t)(s0 + s) * 64 + d];
        }
        // load lr2 chunk
        for (int f = tid; f < 2048; f += 128) {
            int n = f >> 5, s = f & 31;
            sm.lr2s[n][s] = lr2base[(size_t)n * T_ + s0 + s];
        }
        __syncthreads();

        #pragma unroll
        for (int rr = 0; rr < 8; rr++) {
            const int lr = w * 8 + rr;
            const int t = t0 + lr;
            const int s = s0 + lane;
            float wv;
            if (s <= t) {
                float dot = 0.0f;
                #pragma unroll
                for (int d = 0; d < 64; d++) dot += sm.q[lr][d] * sm.kT[d][lane];
                int delta = s - t;                       // <= 0
                int id = (delta < -32) ? 0 : (delta + 32);
                float raw = (dot + sm.qr[lr][id]) * inv_sqrt_d;
                int rv_ = relbase[(size_t)t * T_ + s];
                float x2 = raw * sm.relw[rv_];
                x2 += tdsbase[(size_t)t * T_ + s];
                int lm = lmbase[(size_t)t * T_ + s];
                x2 += sm.lr1[lr][lm] + sm.lr2s[lm][lane];
                wv = x2 * inv_sqrt2;
            } else {
                wv = -1e30f;
            }
            // online softmax (warp over 32 keys)
            float mc = wv;
            #pragma unroll
            for (int o = 16; o; o >>= 1)
                mc = fmaxf(mc, __shfl_xor_sync(0xffffffffu, mc, o));
            float m_new = fmaxf(m_[rr], mc);
            float scale = __expf(m_[rr] - m_new);
            float p = __expf(wv - m_new);
            float ps = p;
            #pragma unroll
            for (int o = 16; o; o >>= 1)
                ps += __shfl_xor_sync(0xffffffffu, ps, o);
            l_[rr] = l_[rr] * scale + ps;
            m_[rr] = m_new;
            acc0[rr] *= scale; acc1[rr] *= scale;

            // accumulate p * (v[s] + rel_v[id(t,s)])
            #pragma unroll
            for (int si = 0; si < 32; si++) {
                float pb = __shfl_sync(0xffffffffu, p, si);
                if (pb != 0.0f) {
                    int ss = s0 + si;
                    int delta2 = ss - t;
                    int id2 = (delta2 < -32) ? 0 : (delta2 + 32);
                    acc0[rr] += pb * (sm.v[si][lane]      + sm.rv[id2][lane]);
                    acc1[rr] += pb * (sm.v[si][lane + 32] + sm.rv[id2][lane + 32]);
                }
            }
        }
    }

    // epilogue: write [B,T,H*D]
    #pragma unroll
    for (int rr = 0; rr < 8; rr++) {
        int t = t0 + w * 8 + rr;
        float invl = 1.0f / l_[rr];
        float* orow = g_att + (size_t)(b * T_ + t) * NX_ + h * 64;
        orow[lane]      = acc0[rr] * invl;
        orow[lane + 32] = acc1[rr] * invl;
    }
}

// ---------------- Kernel 4: output projection GEMM ----------------
// out[m,n] = sum_k att[m,k]*W[k,n] + bias[n];  M=4096, K=1024, N=1024
__global__ __launch_bounds__(256) void proj_gemm(
    const float* __restrict__ W, const float* __restrict__ bias,
    float* __restrict__ out)
{
    __shared__ float As[8][128];
    __shared__ float Bs[8][128];
    const int n0 = blockIdx.x * 128;
    const int m0 = blockIdx.y * 128;
    const int tid = threadIdx.x;
    const int tx = tid & 15, ty = tid >> 4;
    const int arow = tid >> 1, acol = (tid & 1) * 4;
    const int brow = tid >> 5, bcol = (tid & 31) * 4;

    float acc[8][8];
    #pragma unroll
    for (int i = 0; i < 8; i++)
        #pragma unroll
        for (int j = 0; j < 8; j++) acc[i][j] = 0.0f;

    for (int k0 = 0; k0 < 1024; k0 += 8) {
        float4 a = *(const float4*)(g_att + (size_t)(m0 + arow) * 1024 + k0 + acol);
        As[acol + 0][arow] = a.x; As[acol + 1][arow] = a.y;
        As[acol + 2][arow] = a.z; As[acol + 3][arow] = a.w;
        float4 b4 = *(const float4*)(W + (size_t)(k0 + brow) * 1024 + n0 + bcol);
        *(float4*)(&Bs[brow][bcol]) = b4;
        __syncthreads();
        #pragma unroll
        for (int kk = 0; kk < 8; kk++) {
            float ar[8], br[8];
            #pragma unroll
            for (int i = 0; i < 8; i++) ar[i] = As[kk][ty * 8 + i];
            #pragma unroll
            for (int j = 0; j < 8; j++) br[j] = Bs[kk][tx * 8 + j];
            #pragma unroll
            for (int i = 0; i < 8; i++)
                #pragma unroll
                for (int j = 0; j < 8; j++) acc[i][j] += ar[i] * br[j];
        }
        __syncthreads();
    }
    #pragma unroll
    for (int i = 0; i < 8; i++) {
        int m = m0 + ty * 8 + i;
        #pragma unroll
        for (int j = 0; j < 8; j++) {
            int n = n0 + tx * 8 + j;
            out[(size_t)m * 1024 + n] = acc[i][j] + bias[n];
        }
    }
}

// ---------------- launch ----------------
extern "C" void kernel_launch(void* const* d_in, const int* in_sizes, int n_in,
                              void* d_out, int out_size)
{
    const float* x          = (const float*)d_in[0];
    const int*   rel        = (const int*)  d_in[1];
    const float* tds        = (const float*)d_in[2];
    const float* LR_Q       = (const float*)d_in[3];
    const float* LR_K       = (const float*)d_in[4];
    const int*   LR_map     = (const int*)  d_in[5];
    const float* c_attn_w   = (const float*)d_in[6];
    const float* c_attn_b   = (const float*)d_in[7];
    const float* c_proj_w   = (const float*)d_in[8];
    const float* c_proj_b   = (const float*)d_in[9];
    const float* rel_w_emb  = (const float*)d_in[10];
    const float* rel_k_emb  = (const float*)d_in[11];
    const float* rel_v_emb  = (const float*)d_in[12];
    float* out = (float*)d_out;

    cudaFuncSetAttribute(attn_kernel, cudaFuncAttributeMaxDynamicSharedMemorySize,
                         (int)sizeof(AttSmem));

    qkv_gemm<<<dim3(24, 32), 256>>>(x, c_attn_w, c_attn_b);
    lr2_kernel<<<dim3(16, 64), 256>>>(LR_Q);
    attn_kernel<<<dim3(32, 64), 128, sizeof(AttSmem)>>>(
        rel, tds, LR_K, LR_map, rel_w_emb, rel_k_emb, rel_v_emb);
    proj_gemm<<<dim3(8, 32), 256>>>(c_proj_w, c_proj_b, out);
}

// round 3
// speedup vs baseline: 1.3756x; 1.3756x over previous
#include <cuda_runtime.h>
#include <stdint.h>

#define B_ 4
#define T_ 1024
#define NX_ 1024
#define H_ 16
#define D_ 64
#define KMAX_ 32
#define NLOC_ 64

// ---------------- scratch ----------------
__device__ float g_q[B_*H_*T_*D_];
__device__ float g_k[B_*H_*T_*D_];
__device__ float g_v[B_*H_*T_*D_];
__device__ float g_lr2[B_*H_*NLOC_*T_];
__device__ float g_att[B_*T_*NX_];

// ---------------- Kernel 1: QKV GEMM (double-buffered) ----------------
__global__ __launch_bounds__(256) void qkv_gemm(
    const float* __restrict__ X, const float* __restrict__ W,
    const float* __restrict__ bias)
{
    __shared__ float As[2][8][128];
    __shared__ float Bs[2][8][128];
    const int n0 = blockIdx.x * 128;
    const int m0 = blockIdx.y * 128;
    const int tid = threadIdx.x;
    const int tx = tid & 15, ty = tid >> 4;
    const int arow = tid >> 1, acol = (tid & 1) * 4;
    const int brow = tid >> 5, bcol = (tid & 31) * 4;

    const float* Aptr = X + (size_t)(m0 + arow) * 1024 + acol;
    const float* Bptr = W + (size_t)brow * 3072 + n0 + bcol;

    float4 ra = *(const float4*)(Aptr);
    float4 rb = *(const float4*)(Bptr);

    float acc[8][8];
    #pragma unroll
    for (int i = 0; i < 8; i++)
        #pragma unroll
        for (int j = 0; j < 8; j++) acc[i][j] = 0.0f;

    As[0][acol+0][arow] = ra.x; As[0][acol+1][arow] = ra.y;
    As[0][acol+2][arow] = ra.z; As[0][acol+3][arow] = ra.w;
    *(float4*)&Bs[0][brow][bcol] = rb;
    __syncthreads();

    int buf = 0;
    for (int k0 = 0; k0 < 1024; k0 += 8) {
        if (k0 + 8 < 1024) {
            ra = *(const float4*)(Aptr + k0 + 8);
            rb = *(const float4*)(Bptr + (size_t)(k0 + 8) * 3072);
        }
        #pragma unroll
        for (int kk = 0; kk < 8; kk++) {
            float4 a0 = *(const float4*)&As[buf][kk][ty*4];
            float4 a1 = *(const float4*)&As[buf][kk][64 + ty*4];
            float4 b0 = *(const float4*)&Bs[buf][kk][tx*4];
            float4 b1 = *(const float4*)&Bs[buf][kk][64 + tx*4];
            float av[8] = {a0.x,a0.y,a0.z,a0.w,a1.x,a1.y,a1.z,a1.w};
            float bv[8] = {b0.x,b0.y,b0.z,b0.w,b1.x,b1.y,b1.z,b1.w};
            #pragma unroll
            for (int i = 0; i < 8; i++)
                #pragma unroll
                for (int j = 0; j < 8; j++)
                    acc[i][j] = fmaf(av[i], bv[j], acc[i][j]);
        }
        if (k0 + 8 < 1024) {
            int nb = buf ^ 1;
            As[nb][acol+0][arow] = ra.x; As[nb][acol+1][arow] = ra.y;
            As[nb][acol+2][arow] = ra.z; As[nb][acol+3][arow] = ra.w;
            *(float4*)&Bs[nb][brow][bcol] = rb;
        }
        __syncthreads();
        buf ^= 1;
    }

    #pragma unroll
    for (int i = 0; i < 8; i++) {
        int m = m0 + ((i < 4) ? (ty*4 + i) : (64 + ty*4 + i - 4));
        int b = m >> 10, t = m & 1023;
        #pragma unroll
        for (int j = 0; j < 8; j++) {
            int n = n0 + ((j < 4) ? (tx*4 + j) : (64 + tx*4 + j - 4));
            float val = acc[i][j] + bias[n];
            int which = n >> 10;
            int c = n & 1023;
            int hh = c >> 6, dd = c & 63;
            float* dst = (which == 0) ? g_q : (which == 1) ? g_k : g_v;
            dst[(size_t)(((b * H_) + hh) * T_ + t) * D_ + dd] = val;
        }
    }
}

// ---------------- Kernel 2: lr2[b,h,n,s] ----------------
__global__ __launch_bounds__(256) void lr2_kernel(const float* __restrict__ LR_Q)
{
    __shared__ float LQ[64][64];
    __shared__ float Ks[64][65];
    const int bh = blockIdx.y;
    const int h = bh & (H_ - 1);
    const int s0 = blockIdx.x * 64;
    const int tid = threadIdx.x;

    for (int it = 0; it < 16; it++) {
        int f = it * 256 + tid;
        LQ[f >> 6][f & 63] = LR_Q[(size_t)(h * 64 + (f >> 6)) * 64 + (f & 63)];
    }
    for (int it = 0; it < 16; it++) {
        int f = it * 256 + tid;
        Ks[f >> 6][f & 63] = g_k[(size_t)(bh * T_ + s0 + (f >> 6)) * 64 + (f & 63)];
    }
    __syncthreads();

    const int s = tid & 63;
    const int g = tid >> 6;
    float acc[16];
    #pragma unroll
    for (int nn = 0; nn < 16; nn++) acc[nn] = 0.0f;
    for (int d = 0; d < 64; d++) {
        float kv = Ks[s][d];
        #pragma unroll
        for (int nn = 0; nn < 16; nn++) acc[nn] += LQ[g * 16 + nn][d] * kv;
    }
    #pragma unroll
    for (int nn = 0; nn < 16; nn++)
        g_lr2[(size_t)(bh * 64 + g * 16 + nn) * T_ + s0 + s] = acc[nn] * 0.125f;
}

// ---------------- Kernel 3: fused attention ----------------
// NOTE: every member that is accessed through float4/float2 casts is
// explicitly 16-byte aligned (the R2 failure was sm.q landing at
// offset%16==8 because rvp's size is not a multiple of 16).
struct __align__(16) AttSmem {
    float4 kq[32][17];                 // k chunk: [s][dq]
    alignas(16) float q[32][64];       // query tile (float4-read)
    alignas(16) float ps[4][32][12];   // p tile per warp (float4 r/w)
    alignas(16) float2 vp[32][33];     // v pairs
    alignas(16) float2 rvp[33][33];    // rel_v pairs
    alignas(16) float qr[32][33];
    alignas(16) float lr1[32][64];
    alignas(16) float lr2s[64][33];
    alignas(16) float relw[64];
};

__global__ __launch_bounds__(128) void attn_kernel(
    const int* __restrict__ rel, const float* __restrict__ tds,
    const float* __restrict__ LR_K, const int* __restrict__ LR_map,
    const float* __restrict__ rel_w_emb, const float* __restrict__ rel_k_emb,
    const float* __restrict__ rel_v_emb)
{
    extern __shared__ char smem_raw[];
    AttSmem& sm = *reinterpret_cast<AttSmem*>(smem_raw);

    const int bx = (int)gridDim.x - 1 - (int)blockIdx.x;  // heavy tiles first
    const int t0 = bx * 32;
    const int bh = blockIdx.y;
    const int b = bh >> 4, h = bh & 15;
    const int tid = threadIdx.x;
    const int lane = tid & 31, w = tid >> 5;

    const float* qbase = g_q + (size_t)bh * T_ * D_;
    const float* kbase = g_k + (size_t)bh * T_ * D_;
    const float* vbase = g_v + (size_t)bh * T_ * D_;
    const float* lr2base = g_lr2 + (size_t)bh * NLOC_ * T_;
    const int* relbase = rel + (size_t)b * T_ * T_;
    const int* lmbase = LR_map + (size_t)b * T_ * T_;
    const float* tdsbase = tds + (size_t)bh * T_ * T_;

    // ---- prologue ----
    for (int f = tid; f < 32 * 64; f += 128)
        sm.q[f >> 6][f & 63] = qbase[(size_t)t0 * 64 + f];
    if (tid < 64) sm.relw[tid] = rel_w_emb[tid * H_ + h];
    for (int f = tid; f < 33 * 32; f += 128) {
        int id = f >> 5, j = f & 31;
        sm.rvp[id][j] = make_float2(rel_v_emb[id * 64 + j], rel_v_emb[id * 64 + j + 32]);
    }
    __syncthreads();

    for (int task = tid; task < 32 * 33; task += 128) {
        int r = task / 33, id = task % 33;
        const float* rk = rel_k_emb + id * 64;
        float a = 0.0f;
        #pragma unroll 16
        for (int d = 0; d < 64; d++) a += sm.q[r][d] * rk[d];
        sm.qr[r][id] = a;
    }
    for (int task = tid; task < 32 * 64; task += 128) {
        int r = task >> 6, n = task & 63;
        const float* lk = LR_K + (size_t)(h * 64 + n) * 64;
        float a = 0.0f;
        #pragma unroll 16
        for (int d = 0; d < 64; d++) a += sm.q[r][d] * lk[d];
        sm.lr1[r][n] = a * 0.125f;
    }
    __syncthreads();

    float qr0[8];
    #pragma unroll
    for (int rr = 0; rr < 8; rr++) qr0[rr] = sm.qr[w * 8 + rr][0];

    float m_[8], l_[8], rvacc[8], acc0[8], acc1[8];
    #pragma unroll
    for (int rr = 0; rr < 8; rr++) {
        m_[rr] = -1e30f; l_[rr] = 0.0f; rvacc[rr] = 0.0f;
        acc0[rr] = 0.0f; acc1[rr] = 0.0f;
    }

    for (int c = 0; c <= bx; c++) {
        const int s0 = c * 32;
        const bool far = (c + 2 <= bx);   // all rel ids clamp to 0
        __syncthreads();

        for (int f = tid; f < 512; f += 128) {          // k: 32 x 16 float4
            int s = f >> 4, dq = f & 15;
            sm.kq[s][dq] = *(const float4*)(kbase + (size_t)(s0 + s) * 64 + dq * 4);
        }
        for (int f = tid; f < 1024; f += 128) {         // v pairs
            int s = f >> 5, j = f & 31;
            const float* vr = vbase + (size_t)(s0 + s) * 64;
            sm.vp[s][j] = make_float2(vr[j], vr[j + 32]);
        }
        for (int f = tid; f < 2048; f += 128) {         // lr2 chunk
            int n = f >> 5, s = f & 31;
            sm.lr2s[n][s] = lr2base[(size_t)n * T_ + s0 + s];
        }
        __syncthreads();

        // prefetch per-pair global values (batched for MLP)
        int relv[8], lmv[8]; float tdsv[8];
        #pragma unroll
        for (int rr = 0; rr < 8; rr++) {
            size_t off = (size_t)(t0 + w * 8 + rr) * T_ + s0 + lane;
            relv[rr] = relbase[off];
            lmv[rr]  = lmbase[off];
            tdsv[rr] = tdsbase[off];
        }

        // scores: lane = key s, 8 rows per warp
        float sc[8];
        #pragma unroll
        for (int rr = 0; rr < 8; rr++) sc[rr] = 0.0f;
        #pragma unroll
        for (int dq = 0; dq < 16; dq++) {
            float4 kv = sm.kq[lane][dq];
            #pragma unroll
            for (int rr = 0; rr < 8; rr++) {
                float4 qv = *(const float4*)&sm.q[w * 8 + rr][dq * 4];
                sc[rr] = fmaf(qv.x, kv.x, fmaf(qv.y, kv.y,
                          fmaf(qv.z, kv.z, fmaf(qv.w, kv.w, sc[rr]))));
            }
        }

        float pbuf[8];
        #pragma unroll
        for (int rr = 0; rr < 8; rr++) {
            const int lr = w * 8 + rr;
            const int t = t0 + lr;
            const int s = s0 + lane;
            float wv;
            if (s <= t) {
                float qadd;
                if (far) qadd = qr0[rr];
                else { int id = s - t + 32; if (id < 0) id = 0; qadd = sm.qr[lr][id]; }
                float raw = (sc[rr] + qadd) * 0.125f;
                float x2 = fmaf(raw, sm.relw[relv[rr]], tdsv[rr]);
                int lm = lmv[rr];
                x2 += sm.lr1[lr][lm] + sm.lr2s[lm][lane];
                wv = x2 * 0.70710678118f;
            } else {
                wv = -1e30f;
            }
            float mc = wv;
            #pragma unroll
            for (int o = 16; o; o >>= 1)
                mc = fmaxf(mc, __shfl_xor_sync(0xffffffffu, mc, o));
            float m_new = fmaxf(m_[rr], mc);
            float scale = __expf(m_[rr] - m_new);
            float p = __expf(wv - m_new);
            float psum = p;
            #pragma unroll
            for (int o = 16; o; o >>= 1)
                psum += __shfl_xor_sync(0xffffffffu, psum, o);
            l_[rr] = l_[rr] * scale + psum;
            rvacc[rr] = rvacc[rr] * scale + (far ? psum : 0.0f);
            m_[rr] = m_new;
            acc0[rr] *= scale; acc1[rr] *= scale;
            pbuf[rr] = p;
        }

        *(float4*)&sm.ps[w][lane][0] = make_float4(pbuf[0], pbuf[1], pbuf[2], pbuf[3]);
        *(float4*)&sm.ps[w][lane][4] = make_float4(pbuf[4], pbuf[5], pbuf[6], pbuf[7]);
        __syncwarp();

        if (far) {
            #pragma unroll 4
            for (int si = 0; si < 32; si++) {
                float2 vv = sm.vp[si][lane];
                float4 pa = *(const float4*)&sm.ps[w][si][0];
                float4 pb = *(const float4*)&sm.ps[w][si][4];
                acc0[0] = fmaf(pa.x, vv.x, acc0[0]); acc1[0] = fmaf(pa.x, vv.y, acc1[0]);
                acc0[1] = fmaf(pa.y, vv.x, acc0[1]); acc1[1] = fmaf(pa.y, vv.y, acc1[1]);
                acc0[2] = fmaf(pa.z, vv.x, acc0[2]); acc1[2] = fmaf(pa.z, vv.y, acc1[2]);
                acc0[3] = fmaf(pa.w, vv.x, acc0[3]); acc1[3] = fmaf(pa.w, vv.y, acc1[3]);
                acc0[4] = fmaf(pb.x, vv.x, acc0[4]); acc1[4] = fmaf(pb.x, vv.y, acc1[4]);
                acc0[5] = fmaf(pb.y, vv.x, acc0[5]); acc1[5] = fmaf(pb.y, vv.y, acc1[5]);
                acc0[6] = fmaf(pb.z, vv.x, acc0[6]); acc1[6] = fmaf(pb.z, vv.y, acc1[6]);
                acc0[7] = fmaf(pb.w, vv.x, acc0[7]); acc1[7] = fmaf(pb.w, vv.y, acc1[7]);
            }
        } else {
            for (int si = 0; si < 32; si++) {
                float2 vv = sm.vp[si][lane];
                float4 pa = *(const float4*)&sm.ps[w][si][0];
                float4 pb = *(const float4*)&sm.ps[w][si][4];
                float pr[8] = {pa.x, pa.y, pa.z, pa.w, pb.x, pb.y, pb.z, pb.w};
                int idb = s0 + si - (t0 + w * 8) + 32;  // id for rr=0
                #pragma unroll
                for (int rr = 0; rr < 8; rr++) {
                    int id2 = idb - rr;
                    id2 = id2 < 0 ? 0 : (id2 > 32 ? 32 : id2);
                    float2 rv2 = sm.rvp[id2][lane];
                    acc0[rr] = fmaf(pr[rr], vv.x + rv2.x, acc0[rr]);
                    acc1[rr] = fmaf(pr[rr], vv.y + rv2.y, acc1[rr]);
                }
            }
        }
    }

    float2 rv0 = sm.rvp[0][lane];
    #pragma unroll
    for (int rr = 0; rr < 8; rr++) {
        int t = t0 + w * 8 + rr;
        float invl = 1.0f / l_[rr];
        float* orow = g_att + (size_t)(b * T_ + t) * NX_ + h * 64;
        orow[lane]      = (acc0[rr] + rvacc[rr] * rv0.x) * invl;
        orow[lane + 32] = (acc1[rr] + rvacc[rr] * rv0.y) * invl;
    }
}

// ---------------- Kernel 4: output projection (double-buffered) ----------------
__global__ __launch_bounds__(256) void proj_gemm(
    const float* __restrict__ W, const float* __restrict__ bias,
    float* __restrict__ out)
{
    __shared__ float As[2][8][128];
    __shared__ float Bs[2][8][128];
    const int n0 = blockIdx.x * 128;
    const int m0 = blockIdx.y * 128;
    const int tid = threadIdx.x;
    const int tx = tid & 15, ty = tid >> 4;
    const int arow = tid >> 1, acol = (tid & 1) * 4;
    const int brow = tid >> 5, bcol = (tid & 31) * 4;

    const float* Aptr = g_att + (size_t)(m0 + arow) * 1024 + acol;
    const float* Bptr = W + (size_t)brow * 1024 + n0 + bcol;

    float4 ra = *(const float4*)(Aptr);
    float4 rb = *(const float4*)(Bptr);

    float acc[8][8];
    #pragma unroll
    for (int i = 0; i < 8; i++)
        #pragma unroll
        for (int j = 0; j < 8; j++) acc[i][j] = 0.0f;

    As[0][acol+0][arow] = ra.x; As[0][acol+1][arow] = ra.y;
    As[0][acol+2][arow] = ra.z; As[0][acol+3][arow] = ra.w;
    *(float4*)&Bs[0][brow][bcol] = rb;
    __syncthreads();

    int buf = 0;
    for (int k0 = 0; k0 < 1024; k0 += 8) {
        if (k0 + 8 < 1024) {
            ra = *(const float4*)(Aptr + k0 + 8);
            rb = *(const float4*)(Bptr + (size_t)(k0 + 8) * 1024);
        }
        #pragma unroll
        for (int kk = 0; kk < 8; kk++) {
            float4 a0 = *(const float4*)&As[buf][kk][ty*4];
            float4 a1 = *(const float4*)&As[buf][kk][64 + ty*4];
            float4 b0 = *(const float4*)&Bs[buf][kk][tx*4];
            float4 b1 = *(const float4*)&Bs[buf][kk][64 + tx*4];
            float av[8] = {a0.x,a0.y,a0.z,a0.w,a1.x,a1.y,a1.z,a1.w};
            float bv[8] = {b0.x,b0.y,b0.z,b0.w,b1.x,b1.y,b1.z,b1.w};
            #pragma unroll
            for (int i = 0; i < 8; i++)
                #pragma unroll
                for (int j = 0; j < 8; j++)
                    acc[i][j] = fmaf(av[i], bv[j], acc[i][j]);
        }
        if (k0 + 8 < 1024) {
            int nb = buf ^ 1;
            As[nb][acol+0][arow] = ra.x; As[nb][acol+1][arow] = ra.y;
            As[nb][acol+2][arow] = ra.z; As[nb][acol+3][arow] = ra.w;
            *(float4*)&Bs[nb][brow][bcol] = rb;
        }
        __syncthreads();
        buf ^= 1;
    }

    float4 bl0 = *(const float4*)(bias + n0 + tx*4);
    float4 bl1 = *(const float4*)(bias + n0 + 64 + tx*4);
    #pragma unroll
    for (int i = 0; i < 8; i++) {
        int m = m0 + ((i < 4) ? (ty*4 + i) : (64 + ty*4 + i - 4));
        float4 o0 = make_float4(acc[i][0]+bl0.x, acc[i][1]+bl0.y, acc[i][2]+bl0.z, acc[i][3]+bl0.w);
        float4 o1 = make_float4(acc[i][4]+bl1.x, acc[i][5]+bl1.y, acc[i][6]+bl1.z, acc[i][7]+bl1.w);
        *(float4*)(out + (size_t)m * 1024 + n0 + tx*4) = o0;
        *(float4*)(out + (size_t)m * 1024 + n0 + 64 + tx*4) = o1;
    }
}

// ---------------- launch ----------------
extern "C" void kernel_launch(void* const* d_in, const int* in_sizes, int n_in,
                              void* d_out, int out_size)
{
    const float* x          = (const float*)d_in[0];
    const int*   rel        = (const int*)  d_in[1];
    const float* tds        = (const float*)d_in[2];
    const float* LR_Q       = (const float*)d_in[3];
    const float* LR_K       = (const float*)d_in[4];
    const int*   LR_map     = (const int*)  d_in[5];
    const float* c_attn_w   = (const float*)d_in[6];
    const float* c_attn_b   = (const float*)d_in[7];
    const float* c_proj_w   = (const float*)d_in[8];
    const float* c_proj_b   = (const float*)d_in[9];
    const float* rel_w_emb  = (const float*)d_in[10];
    const float* rel_k_emb  = (const float*)d_in[11];
    const float* rel_v_emb  = (const float*)d_in[12];
    float* out = (float*)d_out;

    cudaFuncSetAttribute(attn_kernel, cudaFuncAttributeMaxDynamicSharedMemorySize,
                         (int)sizeof(AttSmem));

    qkv_gemm<<<dim3(24, 32), 256>>>(x, c_attn_w, c_attn_b);
    lr2_kernel<<<dim3(16, 64), 256>>>(LR_Q);
    attn_kernel<<<dim3(32, 64), 128, sizeof(AttSmem)>>>(
        rel, tds, LR_K, LR_map, rel_w_emb, rel_k_emb, rel_v_emb);
    proj_gemm<<<dim3(8, 32), 256>>>(c_proj_w, c_proj_b, out);
}

// round 4
// speedup vs baseline: 1.4439x; 1.0496x over previous
#include <cuda_runtime.h>
#include <stdint.h>

#define B_ 4
#define T_ 1024
#define NX_ 1024
#define H_ 16
#define D_ 64
#define KMAX_ 32
#define NLOC_ 64

// ---------------- scratch ----------------
__device__ float g_q[B_*H_*T_*D_];
__device__ float g_k[B_*H_*T_*D_];
__device__ float g_v[B_*H_*T_*D_];
__device__ float g_lr2[B_*H_*NLOC_*T_];
__device__ float g_att[B_*T_*NX_];

// ---------------- Kernel 1: QKV GEMM (double-buffered) ----------------
__global__ __launch_bounds__(256) void qkv_gemm(
    const float* __restrict__ X, const float* __restrict__ W,
    const float* __restrict__ bias)
{
    __shared__ float As[2][8][128];
    __shared__ float Bs[2][8][128];
    const int n0 = blockIdx.x * 128;
    const int m0 = blockIdx.y * 128;
    const int tid = threadIdx.x;
    const int tx = tid & 15, ty = tid >> 4;
    const int arow = tid >> 1, acol = (tid & 1) * 4;
    const int brow = tid >> 5, bcol = (tid & 31) * 4;

    const float* Aptr = X + (size_t)(m0 + arow) * 1024 + acol;
    const float* Bptr = W + (size_t)brow * 3072 + n0 + bcol;

    float4 ra = *(const float4*)(Aptr);
    float4 rb = *(const float4*)(Bptr);

    float acc[8][8];
    #pragma unroll
    for (int i = 0; i < 8; i++)
        #pragma unroll
        for (int j = 0; j < 8; j++) acc[i][j] = 0.0f;

    As[0][acol+0][arow] = ra.x; As[0][acol+1][arow] = ra.y;
    As[0][acol+2][arow] = ra.z; As[0][acol+3][arow] = ra.w;
    *(float4*)&Bs[0][brow][bcol] = rb;
    __syncthreads();

    int buf = 0;
    for (int k0 = 0; k0 < 1024; k0 += 8) {
        if (k0 + 8 < 1024) {
            ra = *(const float4*)(Aptr + k0 + 8);
            rb = *(const float4*)(Bptr + (size_t)(k0 + 8) * 3072);
        }
        #pragma unroll
        for (int kk = 0; kk < 8; kk++) {
            float4 a0 = *(const float4*)&As[buf][kk][ty*4];
            float4 a1 = *(const float4*)&As[buf][kk][64 + ty*4];
            float4 b0 = *(const float4*)&Bs[buf][kk][tx*4];
            float4 b1 = *(const float4*)&Bs[buf][kk][64 + tx*4];
            float av[8] = {a0.x,a0.y,a0.z,a0.w,a1.x,a1.y,a1.z,a1.w};
            float bv[8] = {b0.x,b0.y,b0.z,b0.w,b1.x,b1.y,b1.z,b1.w};
            #pragma unroll
            for (int i = 0; i < 8; i++)
                #pragma unroll
                for (int j = 0; j < 8; j++)
                    acc[i][j] = fmaf(av[i], bv[j], acc[i][j]);
        }
        if (k0 + 8 < 1024) {
            int nb = buf ^ 1;
            As[nb][acol+0][arow] = ra.x; As[nb][acol+1][arow] = ra.y;
            As[nb][acol+2][arow] = ra.z; As[nb][acol+3][arow] = ra.w;
            *(float4*)&Bs[nb][brow][bcol] = rb;
        }
        __syncthreads();
        buf ^= 1;
    }

    #pragma unroll
    for (int i = 0; i < 8; i++) {
        int m = m0 + ((i < 4) ? (ty*4 + i) : (64 + ty*4 + i - 4));
        int b = m >> 10, t = m & 1023;
        #pragma unroll
        for (int j = 0; j < 8; j++) {
            int n = n0 + ((j < 4) ? (tx*4 + j) : (64 + tx*4 + j - 4));
            float val = acc[i][j] + bias[n];
            int which = n >> 10;
            int c = n & 1023;
            int hh = c >> 6, dd = c & 63;
            float* dst = (which == 0) ? g_q : (which == 1) ? g_k : g_v;
            dst[(size_t)(((b * H_) + hh) * T_ + t) * D_ + dd] = val;
        }
    }
}

// ---------------- Kernel 2: lr2[b,h,n,s] ----------------
__global__ __launch_bounds__(256) void lr2_kernel(const float* __restrict__ LR_Q)
{
    __shared__ float LQ[64][64];
    __shared__ float Ks[64][65];
    const int bh = blockIdx.y;
    const int h = bh & (H_ - 1);
    const int s0 = blockIdx.x * 64;
    const int tid = threadIdx.x;

    for (int it = 0; it < 16; it++) {
        int f = it * 256 + tid;
        LQ[f >> 6][f & 63] = LR_Q[(size_t)(h * 64 + (f >> 6)) * 64 + (f & 63)];
    }
    for (int it = 0; it < 16; it++) {
        int f = it * 256 + tid;
        Ks[f >> 6][f & 63] = g_k[(size_t)(bh * T_ + s0 + (f >> 6)) * 64 + (f & 63)];
    }
    __syncthreads();

    const int s = tid & 63;
    const int g = tid >> 6;
    float acc[16];
    #pragma unroll
    for (int nn = 0; nn < 16; nn++) acc[nn] = 0.0f;
    for (int d = 0; d < 64; d++) {
        float kv = Ks[s][d];
        #pragma unroll
        for (int nn = 0; nn < 16; nn++) acc[nn] += LQ[g * 16 + nn][d] * kv;
    }
    #pragma unroll
    for (int nn = 0; nn < 16; nn++)
        g_lr2[(size_t)(bh * 64 + g * 16 + nn) * T_ + s0 + s] = acc[nn] * 0.125f;
}

// ---------------- Kernel 3: fused attention ----------------
// NOTE: every member that is accessed through float4/float2 casts is
// explicitly 16-byte aligned (the R2 failure was sm.q landing at
// offset%16==8 because rvp's size is not a multiple of 16).
struct __align__(16) AttSmem {
    float4 kq[32][17];                 // k chunk: [s][dq]
    alignas(16) float q[32][64];       // query tile (float4-read)
    alignas(16) float ps[4][32][12];   // p tile per warp (float4 r/w)
    alignas(16) float2 vp[32][33];     // v pairs
    alignas(16) float2 rvp[33][33];    // rel_v pairs
    alignas(16) float qr[32][33];
    alignas(16) float lr1[32][64];
    alignas(16) float lr2s[64][33];
    alignas(16) float relw[64];
};

__global__ __launch_bounds__(128) void attn_kernel(
    const int* __restrict__ rel, const float* __restrict__ tds,
    const float* __restrict__ LR_K, const int* __restrict__ LR_map,
    const float* __restrict__ rel_w_emb, const float* __restrict__ rel_k_emb,
    const float* __restrict__ rel_v_emb)
{
    extern __shared__ char smem_raw[];
    AttSmem& sm = *reinterpret_cast<AttSmem*>(smem_raw);

    const int bx = (int)gridDim.x - 1 - (int)blockIdx.x;  // heavy tiles first
    const int t0 = bx * 32;
    const int bh = blockIdx.y;
    const int b = bh >> 4, h = bh & 15;
    const int tid = threadIdx.x;
    const int lane = tid & 31, w = tid >> 5;

    const float* qbase = g_q + (size_t)bh * T_ * D_;
    const float* kbase = g_k + (size_t)bh * T_ * D_;
    const float* vbase = g_v + (size_t)bh * T_ * D_;
    const float* lr2base = g_lr2 + (size_t)bh * NLOC_ * T_;
    const int* relbase = rel + (size_t)b * T_ * T_;
    const int* lmbase = LR_map + (size_t)b * T_ * T_;
    const float* tdsbase = tds + (size_t)bh * T_ * T_;

    // ---- prologue ----
    for (int f = tid; f < 32 * 64; f += 128)
        sm.q[f >> 6][f & 63] = qbase[(size_t)t0 * 64 + f];
    if (tid < 64) sm.relw[tid] = rel_w_emb[tid * H_ + h];
    for (int f = tid; f < 33 * 32; f += 128) {
        int id = f >> 5, j = f & 31;
        sm.rvp[id][j] = make_float2(rel_v_emb[id * 64 + j], rel_v_emb[id * 64 + j + 32]);
    }
    __syncthreads();

    for (int task = tid; task < 32 * 33; task += 128) {
        int r = task / 33, id = task % 33;
        const float* rk = rel_k_emb + id * 64;
        float a = 0.0f;
        #pragma unroll 16
        for (int d = 0; d < 64; d++) a += sm.q[r][d] * rk[d];
        sm.qr[r][id] = a;
    }
    for (int task = tid; task < 32 * 64; task += 128) {
        int r = task >> 6, n = task & 63;
        const float* lk = LR_K + (size_t)(h * 64 + n) * 64;
        float a = 0.0f;
        #pragma unroll 16
        for (int d = 0; d < 64; d++) a += sm.q[r][d] * lk[d];
        sm.lr1[r][n] = a * 0.125f;
    }
    __syncthreads();

    float qr0[8];
    #pragma unroll
    for (int rr = 0; rr < 8; rr++) qr0[rr] = sm.qr[w * 8 + rr][0];

    float m_[8], l_[8], rvacc[8], acc0[8], acc1[8];
    #pragma unroll
    for (int rr = 0; rr < 8; rr++) {
        m_[rr] = -1e30f; l_[rr] = 0.0f; rvacc[rr] = 0.0f;
        acc0[rr] = 0.0f; acc1[rr] = 0.0f;
    }

    for (int c = 0; c <= bx; c++) {
        const int s0 = c * 32;
        const bool far = (c + 2 <= bx);   // all rel ids clamp to 0
        __syncthreads();

        for (int f = tid; f < 512; f += 128) {          // k: 32 x 16 float4
            int s = f >> 4, dq = f & 15;
            sm.kq[s][dq] = *(const float4*)(kbase + (size_t)(s0 + s) * 64 + dq * 4);
        }
        for (int f = tid; f < 1024; f += 128) {         // v pairs
            int s = f >> 5, j = f & 31;
            const float* vr = vbase + (size_t)(s0 + s) * 64;
            sm.vp[s][j] = make_float2(vr[j], vr[j + 32]);
        }
        for (int f = tid; f < 2048; f += 128) {         // lr2 chunk
            int n = f >> 5, s = f & 31;
            sm.lr2s[n][s] = lr2base[(size_t)n * T_ + s0 + s];
        }
        __syncthreads();

        // prefetch per-pair global values (batched for MLP)
        int relv[8], lmv[8]; float tdsv[8];
        #pragma unroll
        for (int rr = 0; rr < 8; rr++) {
            size_t off = (size_t)(t0 + w * 8 + rr) * T_ + s0 + lane;
            relv[rr] = relbase[off];
            lmv[rr]  = lmbase[off];
            tdsv[rr] = tdsbase[off];
        }

        // scores: lane = key s, 8 rows per warp
        float sc[8];
        #pragma unroll
        for (int rr = 0; rr < 8; rr++) sc[rr] = 0.0f;
        #pragma unroll
        for (int dq = 0; dq < 16; dq++) {
            float4 kv = sm.kq[lane][dq];
            #pragma unroll
            for (int rr = 0; rr < 8; rr++) {
                float4 qv = *(const float4*)&sm.q[w * 8 + rr][dq * 4];
                sc[rr] = fmaf(qv.x, kv.x, fmaf(qv.y, kv.y,
                          fmaf(qv.z, kv.z, fmaf(qv.w, kv.w, sc[rr]))));
            }
        }

        float pbuf[8];
        #pragma unroll
        for (int rr = 0; rr < 8; rr++) {
            const int lr = w * 8 + rr;
            const int t = t0 + lr;
            const int s = s0 + lane;
            float wv;
            if (s <= t) {
                float qadd;
                if (far) qadd = qr0[rr];
                else { int id = s - t + 32; if (id < 0) id = 0; qadd = sm.qr[lr][id]; }
                float raw = (sc[rr] + qadd) * 0.125f;
                float x2 = fmaf(raw, sm.relw[relv[rr]], tdsv[rr]);
                int lm = lmv[rr];
                x2 += sm.lr1[lr][lm] + sm.lr2s[lm][lane];
                wv = x2 * 0.70710678118f;
            } else {
                wv = -1e30f;
            }
            float mc = wv;
            #pragma unroll
            for (int o = 16; o; o >>= 1)
                mc = fmaxf(mc, __shfl_xor_sync(0xffffffffu, mc, o));
            float m_new = fmaxf(m_[rr], mc);
            float scale = __expf(m_[rr] - m_new);
            float p = __expf(wv - m_new);
            float psum = p;
            #pragma unroll
            for (int o = 16; o; o >>= 1)
                psum += __shfl_xor_sync(0xffffffffu, psum, o);
            l_[rr] = l_[rr] * scale + psum;
            rvacc[rr] = rvacc[rr] * scale + (far ? psum : 0.0f);
            m_[rr] = m_new;
            acc0[rr] *= scale; acc1[rr] *= scale;
            pbuf[rr] = p;
        }

        *(float4*)&sm.ps[w][lane][0] = make_float4(pbuf[0], pbuf[1], pbuf[2], pbuf[3]);
        *(float4*)&sm.ps[w][lane][4] = make_float4(pbuf[4], pbuf[5], pbuf[6], pbuf[7]);
        __syncwarp();

        if (far) {
            #pragma unroll 4
            for (int si = 0; si < 32; si++) {
                float2 vv = sm.vp[si][lane];
                float4 pa = *(const float4*)&sm.ps[w][si][0];
                float4 pb = *(const float4*)&sm.ps[w][si][4];
                acc0[0] = fmaf(pa.x, vv.x, acc0[0]); acc1[0] = fmaf(pa.x, vv.y, acc1[0]);
                acc0[1] = fmaf(pa.y, vv.x, acc0[1]); acc1[1] = fmaf(pa.y, vv.y, acc1[1]);
                acc0[2] = fmaf(pa.z, vv.x, acc0[2]); acc1[2] = fmaf(pa.z, vv.y, acc1[2]);
                acc0[3] = fmaf(pa.w, vv.x, acc0[3]); acc1[3] = fmaf(pa.w, vv.y, acc1[3]);
                acc0[4] = fmaf(pb.x, vv.x, acc0[4]); acc1[4] = fmaf(pb.x, vv.y, acc1[4]);
                acc0[5] = fmaf(pb.y, vv.x, acc0[5]); acc1[5] = fmaf(pb.y, vv.y, acc1[5]);
                acc0[6] = fmaf(pb.z, vv.x, acc0[6]); acc1[6] = fmaf(pb.z, vv.y, acc1[6]);
                acc0[7] = fmaf(pb.w, vv.x, acc0[7]); acc1[7] = fmaf(pb.w, vv.y, acc1[7]);
            }
        } else {
            for (int si = 0; si < 32; si++) {
                float2 vv = sm.vp[si][lane];
                float4 pa = *(const float4*)&sm.ps[w][si][0];
                float4 pb = *(const float4*)&sm.ps[w][si][4];
                float pr[8] = {pa.x, pa.y, pa.z, pa.w, pb.x, pb.y, pb.z, pb.w};
                int idb = s0 + si - (t0 + w * 8) + 32;  // id for rr=0
                #pragma unroll
                for (int rr = 0; rr < 8; rr++) {
                    int id2 = idb - rr;
                    id2 = id2 < 0 ? 0 : (id2 > 32 ? 32 : id2);
                    float2 rv2 = sm.rvp[id2][lane];
                    acc0[rr] = fmaf(pr[rr], vv.x + rv2.x, acc0[rr]);
                    acc1[rr] = fmaf(pr[rr], vv.y + rv2.y, acc1[rr]);
                }
            }
        }
    }

    float2 rv0 = sm.rvp[0][lane];
    #pragma unroll
    for (int rr = 0; rr < 8; rr++) {
        int t = t0 + w * 8 + rr;
        float invl = 1.0f / l_[rr];
        float* orow = g_att + (size_t)(b * T_ + t) * NX_ + h * 64;
        orow[lane]      = (acc0[rr] + rvacc[rr] * rv0.x) * invl;
        orow[lane + 32] = (acc1[rr] + rvacc[rr] * rv0.y) * invl;
    }
}

// ---------------- Kernel 4: output projection (double-buffered) ----------------
__global__ __launch_bounds__(256) void proj_gemm(
    const float* __restrict__ W, const float* __restrict__ bias,
    float* __restrict__ out)
{
    __shared__ float As[2][8][128];
    __shared__ float Bs[2][8][128];
    const int n0 = blockIdx.x * 128;
    const int m0 = blockIdx.y * 128;
    const int tid = threadIdx.x;
    const int tx = tid & 15, ty = tid >> 4;
    const int arow = tid >> 1, acol = (tid & 1) * 4;
    const int brow = tid >> 5, bcol = (tid & 31) * 4;

    const float* Aptr = g_att + (size_t)(m0 + arow) * 1024 + acol;
    const float* Bptr = W + (size_t)brow * 1024 + n0 + bcol;

    float4 ra = *(const float4*)(Aptr);
    float4 rb = *(const float4*)(Bptr);

    float acc[8][8];
    #pragma unroll
    for (int i = 0; i < 8; i++)
        #pragma unroll
        for (int j = 0; j < 8; j++) acc[i][j] = 0.0f;

    As[0][acol+0][arow] = ra.x; As[0][acol+1][arow] = ra.y;
    As[0][acol+2][arow] = ra.z; As[0][acol+3][arow] = ra.w;
    *(float4*)&Bs[0][brow][bcol] = rb;
    __syncthreads();

    int buf = 0;
    for (int k0 = 0; k0 < 1024; k0 += 8) {
        if (k0 + 8 < 1024) {
            ra = *(const float4*)(Aptr + k0 + 8);
            rb = *(const float4*)(Bptr + (size_t)(k0 + 8) * 1024);
        }
        #pragma unroll
        for (int kk = 0; kk < 8; kk++) {
            float4 a0 = *(const float4*)&As[buf][kk][ty*4];
            float4 a1 = *(const float4*)&As[buf][kk][64 + ty*4];
            float4 b0 = *(const float4*)&Bs[buf][kk][tx*4];
            float4 b1 = *(const float4*)&Bs[buf][kk][64 + tx*4];
            float av[8] = {a0.x,a0.y,a0.z,a0.w,a1.x,a1.y,a1.z,a1.w};
            float bv[8] = {b0.x,b0.y,b0.z,b0.w,b1.x,b1.y,b1.z,b1.w};
            #pragma unroll
            for (int i = 0; i < 8; i++)
                #pragma unroll
                for (int j = 0; j < 8; j++)
                    acc[i][j] = fmaf(av[i], bv[j], acc[i][j]);
        }
        if (k0 + 8 < 1024) {
            int nb = buf ^ 1;
            As[nb][acol+0][arow] = ra.x; As[nb][acol+1][arow] = ra.y;
            As[nb][acol+2][arow] = ra.z; As[nb][acol+3][arow] = ra.w;
            *(float4*)&Bs[nb][brow][bcol] = rb;
        }
        __syncthreads();
        buf ^= 1;
    }

    float4 bl0 = *(const float4*)(bias + n0 + tx*4);
    float4 bl1 = *(const float4*)(bias + n0 + 64 + tx*4);
    #pragma unroll
    for (int i = 0; i < 8; i++) {
        int m = m0 + ((i < 4) ? (ty*4 + i) : (64 + ty*4 + i - 4));
        float4 o0 = make_float4(acc[i][0]+bl0.x, acc[i][1]+bl0.y, acc[i][2]+bl0.z, acc[i][3]+bl0.w);
        float4 o1 = make_float4(acc[i][4]+bl1.x, acc[i][5]+bl1.y, acc[i][6]+bl1.z, acc[i][7]+bl1.w);
        *(float4*)(out + (size_t)m * 1024 + n0 + tx*4) = o0;
        *(float4*)(out + (size_t)m * 1024 + n0 + 64 + tx*4) = o1;
    }
}

// ---------------- launch ----------------
extern "C" void kernel_launch(void* const* d_in, const int* in_sizes, int n_in,
                              void* d_out, int out_size)
{
    const float* x          = (const float*)d_in[0];
    const int*   rel        = (const int*)  d_in[1];
    const float* tds        = (const float*)d_in[2];
    const float* LR_Q       = (const float*)d_in[3];
    const float* LR_K       = (const float*)d_in[4];
    const int*   LR_map     = (const int*)  d_in[5];
    const float* c_attn_w   = (const float*)d_in[6];
    const float* c_attn_b   = (const float*)d_in[7];
    const float* c_proj_w   = (const float*)d_in[8];
    const float* c_proj_b   = (const float*)d_in[9];
    const float* rel_w_emb  = (const float*)d_in[10];
    const float* rel_k_emb  = (const float*)d_in[11];
    const float* rel_v_emb  = (const float*)d_in[12];
    float* out = (float*)d_out;

    cudaFuncSetAttribute(attn_kernel, cudaFuncAttributeMaxDynamicSharedMemorySize,
                         (int)sizeof(AttSmem));

    qkv_gemm<<<dim3(24, 32), 256>>>(x, c_attn_w, c_attn_b);
    lr2_kernel<<<dim3(16, 64), 256>>>(LR_Q);
    attn_kernel<<<dim3(32, 64), 128, sizeof(AttSmem)>>>(
        rel, tds, LR_K, LR_map, rel_w_emb, rel_k_emb, rel_v_emb);
    proj_gemm<<<dim3(8, 32), 256>>>(c_proj_w, c_proj_b, out);
}

// round 5
// speedup vs baseline: 1.4755x; 1.0219x over previous
#include <cuda_runtime.h>
#include <stdint.h>

#define B_ 4
#define T_ 1024
#define NX_ 1024
#define H_ 16
#define D_ 64
#define KMAX_ 32
#define NLOC_ 64

__device__ float g_q[B_*H_*T_*D_];
__device__ float g_k[B_*H_*T_*D_];
__device__ float g_v[B_*H_*T_*D_];
__device__ float g_lr2[B_*H_*NLOC_*T_];
__device__ float g_att[B_*T_*NX_];

// ---------------- Kernel 1: QKV GEMM (double-buffered) ----------------
__global__ __launch_bounds__(256) void qkv_gemm(
    const float* __restrict__ X, const float* __restrict__ W,
    const float* __restrict__ bias)
{
    __shared__ float As[2][8][128];
    __shared__ float Bs[2][8][128];
    const int n0 = blockIdx.x * 128;
    const int m0 = blockIdx.y * 128;
    const int tid = threadIdx.x;
    const int tx = tid & 15, ty = tid >> 4;
    const int arow = tid >> 1, acol = (tid & 1) * 4;
    const int brow = tid >> 5, bcol = (tid & 31) * 4;

    const float* Aptr = X + (size_t)(m0 + arow) * 1024 + acol;
    const float* Bptr = W + (size_t)brow * 3072 + n0 + bcol;

    float4 ra = *(const float4*)(Aptr);
    float4 rb = *(const float4*)(Bptr);

    float acc[8][8];
    #pragma unroll
    for (int i = 0; i < 8; i++)
        #pragma unroll
        for (int j = 0; j < 8; j++) acc[i][j] = 0.0f;

    As[0][acol+0][arow] = ra.x; As[0][acol+1][arow] = ra.y;
    As[0][acol+2][arow] = ra.z; As[0][acol+3][arow] = ra.w;
    *(float4*)&Bs[0][brow][bcol] = rb;
    __syncthreads();

    int buf = 0;
    for (int k0 = 0; k0 < 1024; k0 += 8) {
        if (k0 + 8 < 1024) {
            ra = *(const float4*)(Aptr + k0 + 8);
            rb = *(const float4*)(Bptr + (size_t)(k0 + 8) * 3072);
        }
        #pragma unroll
        for (int kk = 0; kk < 8; kk++) {
            float4 a0 = *(const float4*)&As[buf][kk][ty*4];
            float4 a1 = *(const float4*)&As[buf][kk][64 + ty*4];
            float4 b0 = *(const float4*)&Bs[buf][kk][tx*4];
            float4 b1 = *(const float4*)&Bs[buf][kk][64 + tx*4];
            float av[8] = {a0.x,a0.y,a0.z,a0.w,a1.x,a1.y,a1.z,a1.w};
            float bv[8] = {b0.x,b0.y,b0.z,b0.w,b1.x,b1.y,b1.z,b1.w};
            #pragma unroll
            for (int i = 0; i < 8; i++)
                #pragma unroll
                for (int j = 0; j < 8; j++)
                    acc[i][j] = fmaf(av[i], bv[j], acc[i][j]);
        }
        if (k0 + 8 < 1024) {
            int nb = buf ^ 1;
            As[nb][acol+0][arow] = ra.x; As[nb][acol+1][arow] = ra.y;
            As[nb][acol+2][arow] = ra.z; As[nb][acol+3][arow] = ra.w;
            *(float4*)&Bs[nb][brow][bcol] = rb;
        }
        __syncthreads();
        buf ^= 1;
    }

    #pragma unroll
    for (int i = 0; i < 8; i++) {
        int m = m0 + ((i < 4) ? (ty*4 + i) : (64 + ty*4 + i - 4));
        int b = m >> 10, t = m & 1023;
        #pragma unroll
        for (int j = 0; j < 8; j++) {
            int n = n0 + ((j < 4) ? (tx*4 + j) : (64 + tx*4 + j - 4));
            float val = acc[i][j] + bias[n];
            int which = n >> 10;
            int c = n & 1023;
            int hh = c >> 6, dd = c & 63;
            float* dst = (which == 0) ? g_q : (which == 1) ? g_k : g_v;
            dst[(size_t)(((b * H_) + hh) * T_ + t) * D_ + dd] = val;
        }
    }
}

// ---------------- Kernel 2: lr2 ----------------
__global__ __launch_bounds__(256) void lr2_kernel(const float* __restrict__ LR_Q)
{
    __shared__ float LQ[64][64];
    __shared__ float Ks[64][65];
    const int bh = blockIdx.y;
    const int h = bh & (H_ - 1);
    const int s0 = blockIdx.x * 64;
    const int tid = threadIdx.x;

    for (int it = 0; it < 16; it++) {
        int f = it * 256 + tid;
        LQ[f >> 6][f & 63] = LR_Q[(size_t)(h * 64 + (f >> 6)) * 64 + (f & 63)];
    }
    for (int it = 0; it < 16; it++) {
        int f = it * 256 + tid;
        Ks[f >> 6][f & 63] = g_k[(size_t)(bh * T_ + s0 + (f >> 6)) * 64 + (f & 63)];
    }
    __syncthreads();

    const int s = tid & 63;
    const int g = tid >> 6;
    float acc[16];
    #pragma unroll
    for (int nn = 0; nn < 16; nn++) acc[nn] = 0.0f;
    for (int d = 0; d < 64; d++) {
        float kv = Ks[s][d];
        #pragma unroll
        for (int nn = 0; nn < 16; nn++) acc[nn] += LQ[g * 16 + nn][d] * kv;
    }
    #pragma unroll
    for (int nn = 0; nn < 16; nn++)
        g_lr2[(size_t)(bh * 64 + g * 16 + nn) * T_ + s0 + s] = acc[nn] * 0.125f;
}

// ---------------- Kernel 3: register-tiled fused attention ----------------
// CTA: 128 rows, 256 threads, 64-key chunks. Warp = 16 rows. Thread = 4 rows x 8 keys/d's.
// lane = rg*8+kg. Key/value minor dims stored permuted: pos(x)=((x&4)<<3)+((x>>3)<<2)+(x&3)
// so lane kg's two float4s sit at [kg*4] and [32+kg*4] -> conflict-free LDS.128.
struct __align__(16) AttSmem {
    float qT[64][132];                  // [d][row]
    float temp[64][65];                 // k staging for transpose
    alignas(16) float kT[64][68];       // [d][pos(s)]
    alignas(16) float v[64][68];        // [s][pos(d)]
    alignas(16) float lr2s[64][68];     // [n][s]
    float qr[128][33];
    float lr1[128][64];
    alignas(16) float rvD[33][64];      // [id][pos(d)] : rel_v[id]-rel_v[0]
    alignas(16) float rv0[64];
    float relw[64];
};

__global__ __launch_bounds__(256) void attn_kernel(
    const int* __restrict__ rel, const float* __restrict__ tds,
    const float* __restrict__ LR_K, const int* __restrict__ LR_map,
    const float* __restrict__ rel_w_emb, const float* __restrict__ rel_k_emb,
    const float* __restrict__ rel_v_emb)
{
    extern __shared__ char smem_raw[];
    AttSmem& sm = *reinterpret_cast<AttSmem*>(smem_raw);

    const int bx = 7 - (int)blockIdx.x;          // heavy tiles first
    const int t0 = bx * 128;
    const int bh = blockIdx.y;
    const int b = bh >> 4, h = bh & 15;
    const int tid = threadIdx.x;
    const int lane = tid & 31, w = tid >> 5;
    const int rg = lane >> 3, kg = lane & 7;
    const int lrow0 = w * 16 + rg * 4;
    const int tw = t0 + w * 16;

    const float* qbase = g_q + (size_t)bh * T_ * D_;
    const float* kbase = g_k + (size_t)bh * T_ * D_;
    const float* vbase = g_v + (size_t)bh * T_ * D_;
    const float* lr2base = g_lr2 + (size_t)bh * NLOC_ * T_;
    const int* relbase = rel + (size_t)b * T_ * T_;
    const int* lmbase = LR_map + (size_t)b * T_ * T_;
    const float* tdsbase = tds + (size_t)bh * T_ * T_;

    // ---- prologue ----
    for (int f = tid; f < 8192; f += 256) {
        int lr = f >> 6, d = f & 63;
        sm.qT[d][lr] = qbase[(size_t)(t0 + lr) * 64 + d];
    }
    if (tid < 64) { sm.relw[tid] = rel_w_emb[tid * H_ + h]; sm.rv0[tid] = rel_v_emb[tid]; }
    for (int f = tid; f < 33 * 64; f += 256) {
        int id = f >> 6, d = f & 63;
        int pd = ((d & 4) << 3) + ((d >> 3) << 2) + (d & 3);
        sm.rvD[id][pd] = rel_v_emb[id * 64 + d] - rel_v_emb[d];
    }
    __syncthreads();
    for (int task = tid; task < 128 * 33; task += 256) {
        int lr = task / 33, id = task % 33;
        const float* rk = rel_k_emb + id * 64;
        float a = 0.0f;
        #pragma unroll 8
        for (int d = 0; d < 64; d++) a += sm.qT[d][lr] * rk[d];
        sm.qr[lr][id] = a;
    }
    for (int task = tid; task < 8192; task += 256) {
        int lr = task >> 6, n = task & 63;
        const float* lk = LR_K + (size_t)(h * 64 + n) * 64;
        float a = 0.0f;
        #pragma unroll 8
        for (int d = 0; d < 64; d++) a += sm.qT[d][lr] * lk[d];
        sm.lr1[lr][n] = a * 0.125f;
    }
    __syncthreads();

    float qr0[4];
    #pragma unroll
    for (int r = 0; r < 4; r++) qr0[r] = sm.qr[lrow0 + r][0];

    float m_[4], l_[4], oacc[4][8];
    #pragma unroll
    for (int r = 0; r < 4; r++) {
        m_[r] = -1e30f; l_[r] = 0.0f;
        #pragma unroll
        for (int j = 0; j < 8; j++) oacc[r][j] = 0.0f;
    }

    const int nchunk = 2 * bx + 2;
    for (int c = 0; c < nchunk; c++) {
        const int s0c = c * 64;
        __syncthreads();
        // phase A: k->temp, v/lr2s direct (v with permuted minor)
        for (int f = tid; f < 1024; f += 256) {
            int s = f >> 4, dq = (f & 15) * 4;
            float4 kv = *(const float4*)(kbase + (size_t)(s0c + s) * 64 + dq);
            sm.temp[s][dq] = kv.x; sm.temp[s][dq+1] = kv.y;
            sm.temp[s][dq+2] = kv.z; sm.temp[s][dq+3] = kv.w;
            int pd = ((dq & 4) << 3) + ((dq >> 3) << 2);
            *(float4*)&sm.v[s][pd] = *(const float4*)(vbase + (size_t)(s0c + s) * 64 + dq);
            *(float4*)&sm.lr2s[s][dq] = *(const float4*)(lr2base + (size_t)s * T_ + s0c + dq);
        }
        __syncthreads();
        // phase B: kT[d][pos(s)] = temp[s][d]
        for (int f = tid; f < 1024; f += 256) {
            int d = f & 63, sb = (f >> 6) << 2;
            int ps = ((sb & 4) << 3) + ((sb >> 3) << 2);
            float4 t4 = make_float4(sm.temp[sb][d], sm.temp[sb+1][d],
                                    sm.temp[sb+2][d], sm.temp[sb+3][d]);
            *(float4*)&sm.kT[d][ps] = t4;
        }
        __syncthreads();

        if (s0c <= tw + 15) {
            const bool far = (s0c + 96 <= tw);
            const bool nomask = (s0c + 63 <= tw);

            // ---- scores ----
            float sc[4][8];
            #pragma unroll
            for (int r = 0; r < 4; r++)
                #pragma unroll
                for (int j = 0; j < 8; j++) sc[r][j] = 0.0f;
            #pragma unroll 4
            for (int d = 0; d < 64; d++) {
                float4 qv = *(const float4*)&sm.qT[d][lrow0];
                float4 k0 = *(const float4*)&sm.kT[d][kg * 4];
                float4 k1 = *(const float4*)&sm.kT[d][32 + kg * 4];
                float qa[4] = {qv.x, qv.y, qv.z, qv.w};
                float kv[8] = {k0.x,k0.y,k0.z,k0.w,k1.x,k1.y,k1.z,k1.w};
                #pragma unroll
                for (int r = 0; r < 4; r++)
                    #pragma unroll
                    for (int j = 0; j < 8; j++)
                        sc[r][j] = fmaf(qa[r], kv[j], sc[r][j]);
            }

            // ---- bias + online softmax per row ----
            #pragma unroll
            for (int r = 0; r < 4; r++) {
                const int tr = t0 + lrow0 + r;
                const size_t off = (size_t)tr * T_ + s0c + kg * 8;
                int4 ra4 = *(const int4*)(relbase + off);
                int4 rb4 = *(const int4*)(relbase + off + 4);
                int4 la4 = *(const int4*)(lmbase + off);
                int4 lb4 = *(const int4*)(lmbase + off + 4);
                float4 ta4 = *(const float4*)(tdsbase + off);
                float4 tb4 = *(const float4*)(tdsbase + off + 4);
                int rl[8] = {ra4.x,ra4.y,ra4.z,ra4.w,rb4.x,rb4.y,rb4.z,rb4.w};
                int lm[8] = {la4.x,la4.y,la4.z,la4.w,lb4.x,lb4.y,lb4.z,lb4.w};
                float td[8] = {ta4.x,ta4.y,ta4.z,ta4.w,tb4.x,tb4.y,tb4.z,tb4.w};
                float wv[8];
                #pragma unroll
                for (int j = 0; j < 8; j++) {
                    int sl = kg * 8 + j, s = s0c + sl;
                    float qadd;
                    if (far) qadd = qr0[r];
                    else {
                        int id = s - tr + 32;
                        id = id < 0 ? 0 : (id > 32 ? 32 : id);
                        qadd = sm.qr[lrow0 + r][id];
                    }
                    float x = fmaf((sc[r][j] + qadd) * 0.125f, sm.relw[rl[j]], td[j]);
                    x += sm.lr1[lrow0 + r][lm[j]] + sm.lr2s[lm[j]][sl];
                    wv[j] = x * 0.70710678118f;
                    if (!nomask && s > tr) wv[j] = -1e30f;
                }
                float tmax = wv[0];
                #pragma unroll
                for (int j = 1; j < 8; j++) tmax = fmaxf(tmax, wv[j]);
                tmax = fmaxf(tmax, __shfl_xor_sync(0xffffffffu, tmax, 1));
                tmax = fmaxf(tmax, __shfl_xor_sync(0xffffffffu, tmax, 2));
                tmax = fmaxf(tmax, __shfl_xor_sync(0xffffffffu, tmax, 4));
                float mn = fmaxf(m_[r], tmax);
                float scale = __expf(m_[r] - mn);
                float psum = 0.0f;
                #pragma unroll
                for (int j = 0; j < 8; j++) { sc[r][j] = __expf(wv[j] - mn); psum += sc[r][j]; }
                psum += __shfl_xor_sync(0xffffffffu, psum, 1);
                psum += __shfl_xor_sync(0xffffffffu, psum, 2);
                psum += __shfl_xor_sync(0xffffffffu, psum, 4);
                l_[r] = l_[r] * scale + psum;
                m_[r] = mn;
                #pragma unroll
                for (int j = 0; j < 8; j++) oacc[r][j] *= scale;
            }

            // ---- PV: shuffle-broadcast p ----
            if (far) {
                for (int g = 0; g < 8; g++) {
                    #pragma unroll
                    for (int j = 0; j < 8; j++) {
                        int sl = g * 8 + j;
                        float4 v0 = *(const float4*)&sm.v[sl][kg * 4];
                        float4 v1 = *(const float4*)&sm.v[sl][32 + kg * 4];
                        float vv[8] = {v0.x,v0.y,v0.z,v0.w,v1.x,v1.y,v1.z,v1.w};
                        int src = rg * 8 + g;
                        float pb[4];
                        pb[0] = __shfl_sync(0xffffffffu, sc[0][j], src);
                        pb[1] = __shfl_sync(0xffffffffu, sc[1][j], src);
                        pb[2] = __shfl_sync(0xffffffffu, sc[2][j], src);
                        pb[3] = __shfl_sync(0xffffffffu, sc[3][j], src);
                        #pragma unroll
                        for (int r = 0; r < 4; r++)
                            #pragma unroll
                            for (int j2 = 0; j2 < 8; j2++)
                                oacc[r][j2] = fmaf(pb[r], vv[j2], oacc[r][j2]);
                    }
                }
            } else {
                for (int g = 0; g < 8; g++) {
                    #pragma unroll
                    for (int j = 0; j < 8; j++) {
                        int sl = g * 8 + j;
                        float4 v0 = *(const float4*)&sm.v[sl][kg * 4];
                        float4 v1 = *(const float4*)&sm.v[sl][32 + kg * 4];
                        float vv[8] = {v0.x,v0.y,v0.z,v0.w,v1.x,v1.y,v1.z,v1.w};
                        int src = rg * 8 + g;
                        float pb[4];
                        pb[0] = __shfl_sync(0xffffffffu, sc[0][j], src);
                        pb[1] = __shfl_sync(0xffffffffu, sc[1][j], src);
                        pb[2] = __shfl_sync(0xffffffffu, sc[2][j], src);
                        pb[3] = __shfl_sync(0xffffffffu, sc[3][j], src);
                        #pragma unroll
                        for (int r = 0; r < 4; r++) {
                            int id = s0c + sl - (t0 + lrow0 + r) + 32;
                            id = id < 0 ? 0 : (id > 32 ? 32 : id);
                            float4 w0 = *(const float4*)&sm.rvD[id][kg * 4];
                            float4 w1 = *(const float4*)&sm.rvD[id][32 + kg * 4];
                            float ww[8] = {w0.x,w0.y,w0.z,w0.w,w1.x,w1.y,w1.z,w1.w};
                            #pragma unroll
                            for (int j2 = 0; j2 < 8; j2++)
                                oacc[r][j2] = fmaf(pb[r], vv[j2] + ww[j2], oacc[r][j2]);
                        }
                    }
                }
            }
        }
    }

    // ---- epilogue: out = acc/l + rv0 ----
    float4 r0 = *(const float4*)&sm.rv0[kg * 8];
    float4 r1 = *(const float4*)&sm.rv0[kg * 8 + 4];
    #pragma unroll
    for (int r = 0; r < 4; r++) {
        int tr = t0 + lrow0 + r;
        float invl = 1.0f / l_[r];
        float* orow = g_att + (size_t)(b * T_ + tr) * NX_ + h * 64 + kg * 8;
        float4 o0 = make_float4(oacc[r][0]*invl + r0.x, oacc[r][1]*invl + r0.y,
                                oacc[r][2]*invl + r0.z, oacc[r][3]*invl + r0.w);
        float4 o1 = make_float4(oacc[r][4]*invl + r1.x, oacc[r][5]*invl + r1.y,
                                oacc[r][6]*invl + r1.z, oacc[r][7]*invl + r1.w);
        *(float4*)(orow) = o0;
        *(float4*)(orow + 4) = o1;
    }
}

// ---------------- Kernel 4: output projection (double-buffered) ----------------
__global__ __launch_bounds__(256) void proj_gemm(
    const float* __restrict__ W, const float* __restrict__ bias,
    float* __restrict__ out)
{
    __shared__ float As[2][8][128];
    __shared__ float Bs[2][8][128];
    const int n0 = blockIdx.x * 128;
    const int m0 = blockIdx.y * 128;
    const int tid = threadIdx.x;
    const int tx = tid & 15, ty = tid >> 4;
    const int arow = tid >> 1, acol = (tid & 1) * 4;
    const int brow = tid >> 5, bcol = (tid & 31) * 4;

    const float* Aptr = g_att + (size_t)(m0 + arow) * 1024 + acol;
    const float* Bptr = W + (size_t)brow * 1024 + n0 + bcol;

    float4 ra = *(const float4*)(Aptr);
    float4 rb = *(const float4*)(Bptr);

    float acc[8][8];
    #pragma unroll
    for (int i = 0; i < 8; i++)
        #pragma unroll
        for (int j = 0; j < 8; j++) acc[i][j] = 0.0f;

    As[0][acol+0][arow] = ra.x; As[0][acol+1][arow] = ra.y;
    As[0][acol+2][arow] = ra.z; As[0][acol+3][arow] = ra.w;
    *(float4*)&Bs[0][brow][bcol] = rb;
    __syncthreads();

    int buf = 0;
    for (int k0 = 0; k0 < 1024; k0 += 8) {
        if (k0 + 8 < 1024) {
            ra = *(const float4*)(Aptr + k0 + 8);
            rb = *(const float4*)(Bptr + (size_t)(k0 + 8) * 1024);
        }
        #pragma unroll
        for (int kk = 0; kk < 8; kk++) {
            float4 a0 = *(const float4*)&As[buf][kk][ty*4];
            float4 a1 = *(const float4*)&As[buf][kk][64 + ty*4];
            float4 b0 = *(const float4*)&Bs[buf][kk][tx*4];
            float4 b1 = *(const float4*)&Bs[buf][kk][64 + tx*4];
            float av[8] = {a0.x,a0.y,a0.z,a0.w,a1.x,a1.y,a1.z,a1.w};
            float bv[8] = {b0.x,b0.y,b0.z,b0.w,b1.x,b1.y,b1.z,b1.w};
            #pragma unroll
            for (int i = 0; i < 8; i++)
                #pragma unroll
                for (int j = 0; j < 8; j++)
                    acc[i][j] = fmaf(av[i], bv[j], acc[i][j]);
        }
        if (k0 + 8 < 1024) {
            int nb = buf ^ 1;
            As[nb][acol+0][arow] = ra.x; As[nb][acol+1][arow] = ra.y;
            As[nb][acol+2][arow] = ra.z; As[nb][acol+3][arow] = ra.w;
            *(float4*)&Bs[nb][brow][bcol] = rb;
        }
        __syncthreads();
        buf ^= 1;
    }

    float4 bl0 = *(const float4*)(bias + n0 + tx*4);
    float4 bl1 = *(const float4*)(bias + n0 + 64 + tx*4);
    #pragma unroll
    for (int i = 0; i < 8; i++) {
        int m = m0 + ((i < 4) ? (ty*4 + i) : (64 + ty*4 + i - 4));
        float4 o0 = make_float4(acc[i][0]+bl0.x, acc[i][1]+bl0.y, acc[i][2]+bl0.z, acc[i][3]+bl0.w);
        float4 o1 = make_float4(acc[i][4]+bl1.x, acc[i][5]+bl1.y, acc[i][6]+bl1.z, acc[i][7]+bl1.w);
        *(float4*)(out + (size_t)m * 1024 + n0 + tx*4) = o0;
        *(float4*)(out + (size_t)m * 1024 + n0 + 64 + tx*4) = o1;
    }
}

// ---------------- launch ----------------
extern "C" void kernel_launch(void* const* d_in, const int* in_sizes, int n_in,
                              void* d_out, int out_size)
{
    const float* x          = (const float*)d_in[0];
    const int*   rel        = (const int*)  d_in[1];
    const float* tds        = (const float*)d_in[2];
    const float* LR_Q       = (const float*)d_in[3];
    const float* LR_K       = (const float*)d_in[4];
    const int*   LR_map     = (const int*)  d_in[5];
    const float* c_attn_w   = (const float*)d_in[6];
    const float* c_attn_b   = (const float*)d_in[7];
    const float* c_proj_w   = (const float*)d_in[8];
    const float* c_proj_b   = (const float*)d_in[9];
    const float* rel_w_emb  = (const float*)d_in[10];
    const float* rel_k_emb  = (const float*)d_in[11];
    const float* rel_v_emb  = (const float*)d_in[12];
    float* out = (float*)d_out;

    cudaFuncSetAttribute(attn_kernel, cudaFuncAttributeMaxDynamicSharedMemorySize,
                         (int)sizeof(AttSmem));

    qkv_gemm<<<dim3(24, 32), 256>>>(x, c_attn_w, c_attn_b);
    lr2_kernel<<<dim3(16, 64), 256>>>(LR_Q);
    attn_kernel<<<dim3(8, 64), 256, sizeof(AttSmem)>>>(
        rel, tds, LR_K, LR_map, rel_w_emb, rel_k_emb, rel_v_emb);
    proj_gemm<<<dim3(8, 32), 256>>>(c_proj_w, c_proj_b, out);
}

// round 6
// speedup vs baseline: 3.2940x; 2.2325x over previous
#include <cuda_runtime.h>
#include <stdint.h>

#define B_ 4
#define T_ 1024
#define NX_ 1024
#define H_ 16
#define D_ 64
#define KMAX_ 32
#define NLOC_ 64

__device__ float g_q[B_*H_*T_*D_];
__device__ float g_k[B_*H_*T_*D_];
__device__ float g_v[B_*H_*T_*D_];
__device__ float g_lr2[B_*H_*NLOC_*T_];
__device__ float g_att[B_*T_*NX_];

// ---------------- Kernel 1: QKV GEMM (double-buffered) ----------------
__global__ __launch_bounds__(256) void qkv_gemm(
    const float* __restrict__ X, const float* __restrict__ W,
    const float* __restrict__ bias)
{
    __shared__ float As[2][8][128];
    __shared__ float Bs[2][8][128];
    const int n0 = blockIdx.x * 128;
    const int m0 = blockIdx.y * 128;
    const int tid = threadIdx.x;
    const int tx = tid & 15, ty = tid >> 4;
    const int arow = tid >> 1, acol = (tid & 1) * 4;
    const int brow = tid >> 5, bcol = (tid & 31) * 4;

    const float* Aptr = X + (size_t)(m0 + arow) * 1024 + acol;
    const float* Bptr = W + (size_t)brow * 3072 + n0 + bcol;

    float4 ra = *(const float4*)(Aptr);
    float4 rb = *(const float4*)(Bptr);

    float acc[8][8];
    #pragma unroll
    for (int i = 0; i < 8; i++)
        #pragma unroll
        for (int j = 0; j < 8; j++) acc[i][j] = 0.0f;

    As[0][acol+0][arow] = ra.x; As[0][acol+1][arow] = ra.y;
    As[0][acol+2][arow] = ra.z; As[0][acol+3][arow] = ra.w;
    *(float4*)&Bs[0][brow][bcol] = rb;
    __syncthreads();

    int buf = 0;
    for (int k0 = 0; k0 < 1024; k0 += 8) {
        if (k0 + 8 < 1024) {
            ra = *(const float4*)(Aptr + k0 + 8);
            rb = *(const float4*)(Bptr + (size_t)(k0 + 8) * 3072);
        }
        #pragma unroll
        for (int kk = 0; kk < 8; kk++) {
            float4 a0 = *(const float4*)&As[buf][kk][ty*4];
            float4 a1 = *(const float4*)&As[buf][kk][64 + ty*4];
            float4 b0 = *(const float4*)&Bs[buf][kk][tx*4];
            float4 b1 = *(const float4*)&Bs[buf][kk][64 + tx*4];
            float av[8] = {a0.x,a0.y,a0.z,a0.w,a1.x,a1.y,a1.z,a1.w};
            float bv[8] = {b0.x,b0.y,b0.z,b0.w,b1.x,b1.y,b1.z,b1.w};
            #pragma unroll
            for (int i = 0; i < 8; i++)
                #pragma unroll
                for (int j = 0; j < 8; j++)
                    acc[i][j] = fmaf(av[i], bv[j], acc[i][j]);
        }
        if (k0 + 8 < 1024) {
            int nb = buf ^ 1;
            As[nb][acol+0][arow] = ra.x; As[nb][acol+1][arow] = ra.y;
            As[nb][acol+2][arow] = ra.z; As[nb][acol+3][arow] = ra.w;
            *(float4*)&Bs[nb][brow][bcol] = rb;
        }
        __syncthreads();
        buf ^= 1;
    }

    #pragma unroll
    for (int i = 0; i < 8; i++) {
        int m = m0 + ((i < 4) ? (ty*4 + i) : (64 + ty*4 + i - 4));
        int b = m >> 10, t = m & 1023;
        #pragma unroll
        for (int j = 0; j < 8; j++) {
            int n = n0 + ((j < 4) ? (tx*4 + j) : (64 + tx*4 + j - 4));
            float val = acc[i][j] + bias[n];
            int which = n >> 10;
            int c = n & 1023;
            int hh = c >> 6, dd = c & 63;
            float* dst = (which == 0) ? g_q : (which == 1) ? g_k : g_v;
            dst[(size_t)(((b * H_) + hh) * T_ + t) * D_ + dd] = val;
        }
    }
}

// ---------------- Kernel 2: lr2 ----------------
__global__ __launch_bounds__(256) void lr2_kernel(const float* __restrict__ LR_Q)
{
    __shared__ float LQ[64][64];
    __shared__ float Ks[64][65];
    const int bh = blockIdx.y;
    const int h = bh & (H_ - 1);
    const int s0 = blockIdx.x * 64;
    const int tid = threadIdx.x;

    for (int it = 0; it < 16; it++) {
        int f = it * 256 + tid;
        LQ[f >> 6][f & 63] = LR_Q[(size_t)(h * 64 + (f >> 6)) * 64 + (f & 63)];
    }
    for (int it = 0; it < 16; it++) {
        int f = it * 256 + tid;
        Ks[f >> 6][f & 63] = g_k[(size_t)(bh * T_ + s0 + (f >> 6)) * 64 + (f & 63)];
    }
    __syncthreads();

    const int s = tid & 63;
    const int g = tid >> 6;
    float acc[16];
    #pragma unroll
    for (int nn = 0; nn < 16; nn++) acc[nn] = 0.0f;
    for (int d = 0; d < 64; d++) {
        float kv = Ks[s][d];
        #pragma unroll
        for (int nn = 0; nn < 16; nn++) acc[nn] += LQ[g * 16 + nn][d] * kv;
    }
    #pragma unroll
    for (int nn = 0; nn < 16; nn++)
        g_lr2[(size_t)(bh * 64 + g * 16 + nn) * T_ + s0 + s] = acc[nn] * 0.125f;
}

// ---------------- Kernel 3: fused attention, 64-row CTA, 2 CTA/SM ----------------
// 256 threads = 8 warps x 8 rows. lane = rg*8+kg. Thread: 2 rows x 8 keys (QK)
// and 2 rows x 8 d's (PV). Keys/d's permuted: pos(x)=((x&4)<<3)+((x>>3)<<2)+(x&3)
// => lane kg covers natural indices kg*8..kg*8+7 via float4 at [kg*4] and [32+kg*4].
struct __align__(16) AttSmem {
    float qT[64][68];     // [d][row]
    float kT[64][68];     // [d][pos(s)]
    float v[64][68];      // [s][pos(d)]
    float lr2s[64][65];   // [n][s]     (stride 65: conflict-free random gather)
    float lr1[64][65];    // [row][n]
    float qr[64][36];     // [row][id]
    float rvD[33][68];    // [id][pos(d)] = rel_v[id]-rel_v[0]
    float rv0[64];
    float relw[64];
};

__global__ void __launch_bounds__(256, 2) attn_kernel(
    const int* __restrict__ rel, const float* __restrict__ tds,
    const float* __restrict__ LR_K, const int* __restrict__ LR_map,
    const float* __restrict__ rel_w_emb, const float* __restrict__ rel_k_emb,
    const float* __restrict__ rel_v_emb)
{
    extern __shared__ char smem_raw[];
    AttSmem& sm = *reinterpret_cast<AttSmem*>(smem_raw);

    const int bid = blockIdx.x;
    const int qt = 15 - (bid >> 6);        // heavy tiles first
    const int bh = bid & 63;
    const int t0 = qt * 64;
    const int b = bh >> 4, h = bh & 15;
    const int tid = threadIdx.x;
    const int lane = tid & 31, w = tid >> 5;
    const int rg = lane >> 3, kg = lane & 7;
    const int lrow0 = w * 8 + rg * 2;

    const float* qbase = g_q + (size_t)bh * T_ * D_;
    const float* kbase = g_k + (size_t)bh * T_ * D_;
    const float* vbase = g_v + (size_t)bh * T_ * D_;
    const float* lr2base = g_lr2 + (size_t)bh * NLOC_ * T_;
    const int* relbase = rel + (size_t)b * T_ * T_;
    const int* lmbase = LR_map + (size_t)b * T_ * T_;
    const float* tdsbase = tds + (size_t)bh * T_ * T_;

    // ---- prologue: qT (transposed), relw, rv0, rvD ----
    for (int f = tid; f < 1024; f += 256) {
        int row = f >> 4, dq = (f & 15) * 4;
        float4 qv = *(const float4*)(qbase + (size_t)(t0 + row) * 64 + dq);
        sm.qT[dq+0][row] = qv.x; sm.qT[dq+1][row] = qv.y;
        sm.qT[dq+2][row] = qv.z; sm.qT[dq+3][row] = qv.w;
    }
    if (tid < 64) { sm.relw[tid] = rel_w_emb[tid * H_ + h]; sm.rv0[tid] = rel_v_emb[tid]; }
    for (int f = tid; f < 33 * 64; f += 256) {
        int id = f >> 6, d = f & 63;
        int pd = ((d & 4) << 3) + ((d >> 3) << 2) + (d & 3);
        sm.rvD[id][pd] = rel_v_emb[id * 64 + d] - rel_v_emb[d];
    }
    __syncthreads();

    // qr: id-major tasks -> rel_k_emb read is lane-broadcast, qT read conflict-free
    for (int task = tid; task < 33 * 64; task += 256) {
        int id = task >> 6, lr = task & 63;
        const float* rk = rel_k_emb + id * 64;
        float a = 0.0f;
        #pragma unroll 8
        for (int d = 0; d < 64; d++) a += sm.qT[d][lr] * rk[d];
        sm.qr[lr][id] = a;
    }
    // lr1: n-major tasks
    for (int task = tid; task < 64 * 64; task += 256) {
        int n = task >> 6, lr = task & 63;
        const float* lk = LR_K + (size_t)(h * 64 + n) * 64;
        float a = 0.0f;
        #pragma unroll 8
        for (int d = 0; d < 64; d++) a += sm.qT[d][lr] * lk[d];
        sm.lr1[lr][n] = a * 0.125f;
    }
    __syncthreads();

    float qr0[2] = { sm.qr[lrow0][0], sm.qr[lrow0 + 1][0] };

    float m_[2] = { -1e30f, -1e30f }, l_[2] = { 0.0f, 0.0f };
    float oacc[2][8];
    #pragma unroll
    for (int r = 0; r < 2; r++)
        #pragma unroll
        for (int j = 0; j < 8; j++) oacc[r][j] = 0.0f;

    const int nchunk = qt + 1;
    for (int c = 0; c < nchunk; c++) {
        const int s0c = c * 64;
        __syncthreads();
        // fill kT (scattered transpose), v, lr2s
        for (int f = tid; f < 1024; f += 256) {
            int s = f >> 4, dq = (f & 15) * 4;
            float4 kv = *(const float4*)(kbase + (size_t)(s0c + s) * 64 + dq);
            int ps = ((s & 4) << 3) + ((s >> 3) << 2) + (s & 3);
            sm.kT[dq+0][ps] = kv.x; sm.kT[dq+1][ps] = kv.y;
            sm.kT[dq+2][ps] = kv.z; sm.kT[dq+3][ps] = kv.w;
            int pd = ((dq & 4) << 3) + ((dq >> 3) << 2);
            *(float4*)&sm.v[s][pd] = *(const float4*)(vbase + (size_t)(s0c + s) * 64 + dq);
            float4 l4 = *(const float4*)(lr2base + (size_t)s * T_ + s0c + dq);
            sm.lr2s[s][dq+0] = l4.x; sm.lr2s[s][dq+1] = l4.y;
            sm.lr2s[s][dq+2] = l4.z; sm.lr2s[s][dq+3] = l4.w;
        }
        __syncthreads();

        const bool diag = (c + 1 == nchunk);            // s0c == t0: needs mask
        const bool far = (s0c + 96 <= t0 + w * 8);      // all rel ids clamp to 0

        // ---- scores: 2 rows x 8 keys ----
        float sc[2][8];
        #pragma unroll
        for (int r = 0; r < 2; r++)
            #pragma unroll
            for (int j = 0; j < 8; j++) sc[r][j] = 0.0f;
        #pragma unroll 4
        for (int d = 0; d < 64; d++) {
            float2 qv = *(const float2*)&sm.qT[d][lrow0];
            float4 k0 = *(const float4*)&sm.kT[d][kg * 4];
            float4 k1 = *(const float4*)&sm.kT[d][32 + kg * 4];
            sc[0][0] = fmaf(qv.x, k0.x, sc[0][0]); sc[1][0] = fmaf(qv.y, k0.x, sc[1][0]);
            sc[0][1] = fmaf(qv.x, k0.y, sc[0][1]); sc[1][1] = fmaf(qv.y, k0.y, sc[1][1]);
            sc[0][2] = fmaf(qv.x, k0.z, sc[0][2]); sc[1][2] = fmaf(qv.y, k0.z, sc[1][2]);
            sc[0][3] = fmaf(qv.x, k0.w, sc[0][3]); sc[1][3] = fmaf(qv.y, k0.w, sc[1][3]);
            sc[0][4] = fmaf(qv.x, k1.x, sc[0][4]); sc[1][4] = fmaf(qv.y, k1.x, sc[1][4]);
            sc[0][5] = fmaf(qv.x, k1.y, sc[0][5]); sc[1][5] = fmaf(qv.y, k1.y, sc[1][5]);
            sc[0][6] = fmaf(qv.x, k1.z, sc[0][6]); sc[1][6] = fmaf(qv.y, k1.z, sc[1][6]);
            sc[0][7] = fmaf(qv.x, k1.w, sc[0][7]); sc[1][7] = fmaf(qv.y, k1.w, sc[1][7]);
        }

        // ---- bias + online softmax per row ----
        #pragma unroll
        for (int r = 0; r < 2; r++) {
            const int lr = lrow0 + r;
            const int tr = t0 + lr;
            const size_t off = (size_t)tr * T_ + s0c + kg * 8;
            float wv[8];
            {
                int4 ra = *(const int4*)(relbase + off);
                int4 la = *(const int4*)(lmbase + off);
                float4 ta = *(const float4*)(tdsbase + off);
                int rl[4] = {ra.x, ra.y, ra.z, ra.w};
                int lm[4] = {la.x, la.y, la.z, la.w};
                float td[4] = {ta.x, ta.y, ta.z, ta.w};
                #pragma unroll
                for (int j = 0; j < 4; j++) {
                    int sl = kg * 8 + j;
                    float qadd;
                    if (far) qadd = qr0[r];
                    else {
                        int id = s0c + sl - tr + 32;
                        id = id < 0 ? 0 : (id > 32 ? 32 : id);
                        qadd = sm.qr[lr][id];
                    }
                    float x = fmaf((sc[r][j] + qadd) * 0.125f, sm.relw[rl[j]], td[j]);
                    x += sm.lr1[lr][lm[j]] + sm.lr2s[lm[j]][sl];
                    wv[j] = x * 0.70710678118f;
                    if (diag && sl > lr) wv[j] = -1e30f;
                }
            }
            {
                int4 ra = *(const int4*)(relbase + off + 4);
                int4 la = *(const int4*)(lmbase + off + 4);
                float4 ta = *(const float4*)(tdsbase + off + 4);
                int rl[4] = {ra.x, ra.y, ra.z, ra.w};
                int lm[4] = {la.x, la.y, la.z, la.w};
                float td[4] = {ta.x, ta.y, ta.z, ta.w};
                #pragma unroll
                for (int j = 0; j < 4; j++) {
                    int sl = kg * 8 + 4 + j;
                    float qadd;
                    if (far) qadd = qr0[r];
                    else {
                        int id = s0c + sl - tr + 32;
                        id = id < 0 ? 0 : (id > 32 ? 32 : id);
                        qadd = sm.qr[lr][id];
                    }
                    float x = fmaf((sc[r][4+j] + qadd) * 0.125f, sm.relw[rl[j]], td[j]);
                    x += sm.lr1[lr][lm[j]] + sm.lr2s[lm[j]][sl];
                    wv[4+j] = x * 0.70710678118f;
                    if (diag && sl > lr) wv[4+j] = -1e30f;
                }
            }
            float tmax = wv[0];
            #pragma unroll
            for (int j = 1; j < 8; j++) tmax = fmaxf(tmax, wv[j]);
            tmax = fmaxf(tmax, __shfl_xor_sync(0xffffffffu, tmax, 1));
            tmax = fmaxf(tmax, __shfl_xor_sync(0xffffffffu, tmax, 2));
            tmax = fmaxf(tmax, __shfl_xor_sync(0xffffffffu, tmax, 4));
            float mn = fmaxf(m_[r], tmax);
            float scale = __expf(m_[r] - mn);
            float psum = 0.0f;
            #pragma unroll
            for (int j = 0; j < 8; j++) { sc[r][j] = __expf(wv[j] - mn); psum += sc[r][j]; }
            psum += __shfl_xor_sync(0xffffffffu, psum, 1);
            psum += __shfl_xor_sync(0xffffffffu, psum, 2);
            psum += __shfl_xor_sync(0xffffffffu, psum, 4);
            l_[r] = l_[r] * scale + psum;
            m_[r] = mn;
            #pragma unroll
            for (int j = 0; j < 8; j++) oacc[r][j] *= scale;
        }

        // ---- PV: shuffle-broadcast p ----
        if (far) {
            for (int g = 0; g < 8; g++) {
                #pragma unroll
                for (int j = 0; j < 8; j++) {
                    int sl = g * 8 + j;
                    float4 v0 = *(const float4*)&sm.v[sl][kg * 4];
                    float4 v1 = *(const float4*)&sm.v[sl][32 + kg * 4];
                    int src = rg * 8 + g;
                    float p0 = __shfl_sync(0xffffffffu, sc[0][j], src);
                    float p1 = __shfl_sync(0xffffffffu, sc[1][j], src);
                    oacc[0][0] = fmaf(p0, v0.x, oacc[0][0]); oacc[1][0] = fmaf(p1, v0.x, oacc[1][0]);
                    oacc[0][1] = fmaf(p0, v0.y, oacc[0][1]); oacc[1][1] = fmaf(p1, v0.y, oacc[1][1]);
                    oacc[0][2] = fmaf(p0, v0.z, oacc[0][2]); oacc[1][2] = fmaf(p1, v0.z, oacc[1][2]);
                    oacc[0][3] = fmaf(p0, v0.w, oacc[0][3]); oacc[1][3] = fmaf(p1, v0.w, oacc[1][3]);
                    oacc[0][4] = fmaf(p0, v1.x, oacc[0][4]); oacc[1][4] = fmaf(p1, v1.x, oacc[1][4]);
                    oacc[0][5] = fmaf(p0, v1.y, oacc[0][5]); oacc[1][5] = fmaf(p1, v1.y, oacc[1][5]);
                    oacc[0][6] = fmaf(p0, v1.z, oacc[0][6]); oacc[1][6] = fmaf(p1, v1.z, oacc[1][6]);
                    oacc[0][7] = fmaf(p0, v1.w, oacc[0][7]); oacc[1][7] = fmaf(p1, v1.w, oacc[1][7]);
                }
            }
        } else {
            for (int g = 0; g < 8; g++) {
                #pragma unroll
                for (int j = 0; j < 8; j++) {
                    int sl = g * 8 + j;
                    float4 v0 = *(const float4*)&sm.v[sl][kg * 4];
                    float4 v1 = *(const float4*)&sm.v[sl][32 + kg * 4];
                    int src = rg * 8 + g;
                    float p0 = __shfl_sync(0xffffffffu, sc[0][j], src);
                    float p1 = __shfl_sync(0xffffffffu, sc[1][j], src);
                    int id0 = s0c + sl - (t0 + lrow0) + 32;
                    id0 = id0 < 0 ? 0 : (id0 > 32 ? 32 : id0);
                    int id1 = s0c + sl - (t0 + lrow0 + 1) + 32;
                    id1 = id1 < 0 ? 0 : (id1 > 32 ? 32 : id1);
                    float4 w00 = *(const float4*)&sm.rvD[id0][kg * 4];
                    float4 w01 = *(const float4*)&sm.rvD[id0][32 + kg * 4];
                    float4 w10 = *(const float4*)&sm.rvD[id1][kg * 4];
                    float4 w11 = *(const float4*)&sm.rvD[id1][32 + kg * 4];
                    oacc[0][0] = fmaf(p0, v0.x + w00.x, oacc[0][0]); oacc[1][0] = fmaf(p1, v0.x + w10.x, oacc[1][0]);
                    oacc[0][1] = fmaf(p0, v0.y + w00.y, oacc[0][1]); oacc[1][1] = fmaf(p1, v0.y + w10.y, oacc[1][1]);
                    oacc[0][2] = fmaf(p0, v0.z + w00.z, oacc[0][2]); oacc[1][2] = fmaf(p1, v0.z + w10.z, oacc[1][2]);
                    oacc[0][3] = fmaf(p0, v0.w + w00.w, oacc[0][3]); oacc[1][3] = fmaf(p1, v0.w + w10.w, oacc[1][3]);
                    oacc[0][4] = fmaf(p0, v1.x + w01.x, oacc[0][4]); oacc[1][4] = fmaf(p1, v1.x + w11.x, oacc[1][4]);
                    oacc[0][5] = fmaf(p0, v1.y + w01.y, oacc[0][5]); oacc[1][5] = fmaf(p1, v1.y + w11.y, oacc[1][5]);
                    oacc[0][6] = fmaf(p0, v1.z + w01.z, oacc[0][6]); oacc[1][6] = fmaf(p1, v1.z + w11.z, oacc[1][6]);
                    oacc[0][7] = fmaf(p0, v1.w + w01.w, oacc[0][7]); oacc[1][7] = fmaf(p1, v1.w + w11.w, oacc[1][7]);
                }
            }
        }
    }

    // ---- epilogue: out = acc/l + rv0 ----
    float4 r0 = *(const float4*)&sm.rv0[kg * 8];
    float4 r1 = *(const float4*)&sm.rv0[kg * 8 + 4];
    #pragma unroll
    for (int r = 0; r < 2; r++) {
        int tr = t0 + lrow0 + r;
        float invl = 1.0f / l_[r];
        float* orow = g_att + (size_t)(b * T_ + tr) * NX_ + h * 64 + kg * 8;
        float4 o0 = make_float4(oacc[r][0]*invl + r0.x, oacc[r][1]*invl + r0.y,
                                oacc[r][2]*invl + r0.z, oacc[r][3]*invl + r0.w);
        float4 o1 = make_float4(oacc[r][4]*invl + r1.x, oacc[r][5]*invl + r1.y,
                                oacc[r][6]*invl + r1.z, oacc[r][7]*invl + r1.w);
        *(float4*)(orow) = o0;
        *(float4*)(orow + 4) = o1;
    }
}

// ---------------- Kernel 4: output projection (double-buffered) ----------------
__global__ __launch_bounds__(256) void proj_gemm(
    const float* __restrict__ W, const float* __restrict__ bias,
    float* __restrict__ out)
{
    __shared__ float As[2][8][128];
    __shared__ float Bs[2][8][128];
    const int n0 = blockIdx.x * 128;
    const int m0 = blockIdx.y * 128;
    const int tid = threadIdx.x;
    const int tx = tid & 15, ty = tid >> 4;
    const int arow = tid >> 1, acol = (tid & 1) * 4;
    const int brow = tid >> 5, bcol = (tid & 31) * 4;

    const float* Aptr = g_att + (size_t)(m0 + arow) * 1024 + acol;
    const float* Bptr = W + (size_t)brow * 1024 + n0 + bcol;

    float4 ra = *(const float4*)(Aptr);
    float4 rb = *(const float4*)(Bptr);

    float acc[8][8];
    #pragma unroll
    for (int i = 0; i < 8; i++)
        #pragma unroll
        for (int j = 0; j < 8; j++) acc[i][j] = 0.0f;

    As[0][acol+0][arow] = ra.x; As[0][acol+1][arow] = ra.y;
    As[0][acol+2][arow] = ra.z; As[0][acol+3][arow] = ra.w;
    *(float4*)&Bs[0][brow][bcol] = rb;
    __syncthreads();

    int buf = 0;
    for (int k0 = 0; k0 < 1024; k0 += 8) {
        if (k0 + 8 < 1024) {
            ra = *(const float4*)(Aptr + k0 + 8);
            rb = *(const float4*)(Bptr + (size_t)(k0 + 8) * 1024);
        }
        #pragma unroll
        for (int kk = 0; kk < 8; kk++) {
            float4 a0 = *(const float4*)&As[buf][kk][ty*4];
            float4 a1 = *(const float4*)&As[buf][kk][64 + ty*4];
            float4 b0 = *(const float4*)&Bs[buf][kk][tx*4];
            float4 b1 = *(const float4*)&Bs[buf][kk][64 + tx*4];
            float av[8] = {a0.x,a0.y,a0.z,a0.w,a1.x,a1.y,a1.z,a1.w};
            float bv[8] = {b0.x,b0.y,b0.z,b0.w,b1.x,b1.y,b1.z,b1.w};
            #pragma unroll
            for (int i = 0; i < 8; i++)
                #pragma unroll
                for (int j = 0; j < 8; j++)
                    acc[i][j] = fmaf(av[i], bv[j], acc[i][j]);
        }
        if (k0 + 8 < 1024) {
            int nb = buf ^ 1;
            As[nb][acol+0][arow] = ra.x; As[nb][acol+1][arow] = ra.y;
            As[nb][acol+2][arow] = ra.z; As[nb][acol+3][arow] = ra.w;
            *(float4*)&Bs[nb][brow][bcol] = rb;
        }
        __syncthreads();
        buf ^= 1;
    }

    float4 bl0 = *(const float4*)(bias + n0 + tx*4);
    float4 bl1 = *(const float4*)(bias + n0 + 64 + tx*4);
    #pragma unroll
    for (int i = 0; i < 8; i++) {
        int m = m0 + ((i < 4) ? (ty*4 + i) : (64 + ty*4 + i - 4));
        float4 o0 = make_float4(acc[i][0]+bl0.x, acc[i][1]+bl0.y, acc[i][2]+bl0.z, acc[i][3]+bl0.w);
        float4 o1 = make_float4(acc[i][4]+bl1.x, acc[i][5]+bl1.y, acc[i][6]+bl1.z, acc[i][7]+bl1.w);
        *(float4*)(out + (size_t)m * 1024 + n0 + tx*4) = o0;
        *(float4*)(out + (size_t)m * 1024 + n0 + 64 + tx*4) = o1;
    }
}

// ---------------- launch ----------------
extern "C" void kernel_launch(void* const* d_in, const int* in_sizes, int n_in,
                              void* d_out, int out_size)
{
    const float* x          = (const float*)d_in[0];
    const int*   rel        = (const int*)  d_in[1];
    const float* tds        = (const float*)d_in[2];
    const float* LR_Q       = (const float*)d_in[3];
    const float* LR_K       = (const float*)d_in[4];
    const int*   LR_map     = (const int*)  d_in[5];
    const float* c_attn_w   = (const float*)d_in[6];
    const float* c_attn_b   = (const float*)d_in[7];
    const float* c_proj_w   = (const float*)d_in[8];
    const float* c_proj_b   = (const float*)d_in[9];
    const float* rel_w_emb  = (const float*)d_in[10];
    const float* rel_k_emb  = (const float*)d_in[11];
    const float* rel_v_emb  = (const float*)d_in[12];
    float* out = (float*)d_out;

    cudaFuncSetAttribute(attn_kernel, cudaFuncAttributeMaxDynamicSharedMemorySize,
                         (int)sizeof(AttSmem));

    qkv_gemm<<<dim3(24, 32), 256>>>(x, c_attn_w, c_attn_b);
    lr2_kernel<<<dim3(16, 64), 256>>>(LR_Q);
    attn_kernel<<<1024, 256, sizeof(AttSmem)>>>(
        rel, tds, LR_K, LR_map, rel_w_emb, rel_k_emb, rel_v_emb);
    proj_gemm<<<dim3(8, 32), 256>>>(c_proj_w, c_proj_b, out);
}

// round 7
// speedup vs baseline: 4.0974x; 1.2439x over previous
#include <cuda_runtime.h>
#include <cuda_bf16.h>
#include <stdint.h>

#define B_ 4
#define T_ 1024
#define NX_ 1024
#define H_ 16
#define D_ 64
#define KMAX_ 32
#define NLOC_ 64

__device__ float g_qkv[B_*T_*3*NX_];        // [b,t, q|k|v interleaved by 1024]
__device__ float g_lr2[B_*H_*NLOC_*T_];
__device__ float g_att[B_*T_*NX_];

// ---------------- bf16 split helper ----------------
__device__ __forceinline__ __nv_bfloat16 bfpart(float x, bool lo) {
    float h = __bfloat162float(__float2bfloat16(x));
    return __float2bfloat16(lo ? (x - h) : x);
}

// ---------------- Kernel: bf16x3 tensor-core GEMM ----------------
// out[M,N] = A[M,1024] @ W[1024,N] + bias, via K'=3072 bf16 GEMM:
//   k' in [0,1024): Ah*Wh, [1024,2048): Ah*Wl, [2048,3072): Al*Wh
// CTA tile 128x128, 8 warps (4m x 2n), warp 32x64, mma.m16n8k16.bf16.
__global__ __launch_bounds__(256) void gemm_bf16x3(
    const float* __restrict__ A, const float* __restrict__ W,
    const float* __restrict__ bias, float* __restrict__ out, int N)
{
    __shared__ __nv_bfloat16 As[2][128][40];   // pitch 40 (80B): LDSM conflict-free
    __shared__ __nv_bfloat16 Bs[2][32][136];   // pitch 136 (272B): conflict-free
    const int n0 = blockIdx.x * 128;
    const int m0 = blockIdx.y * 128;
    const int tid = threadIdx.x;
    const int lane = tid & 31, w = tid >> 5;
    const int wm = (w >> 1) * 32, wn = (w & 1) * 64;

    float acc[2][8][4];
    #pragma unroll
    for (int mt = 0; mt < 2; mt++)
        #pragma unroll
        for (int nt = 0; nt < 8; nt++)
            #pragma unroll
            for (int i = 0; i < 4; i++) acc[mt][nt][i] = 0.0f;

    const int arow = tid >> 3, akq = (tid & 7) * 4;     // +f*32 rows
    const int brow = tid >> 6, bnq = (tid & 63) * 2;    // +f*4 rows, 2 floats per task? no:
    // B: 32x128 fp32 = 4096 = 4 float4/thread: row = idx>>5, nq = (idx&31)*4
    float4 Ar[4], Br[4];

    auto ldg = [&](int i) {
        int sk = (i & 31) * 32;
        #pragma unroll
        for (int f = 0; f < 4; f++) {
            int row = arow + f * 32;
            Ar[f] = *(const float4*)(A + (size_t)(m0 + row) * 1024 + sk + akq);
        }
        #pragma unroll
        for (int f = 0; f < 4; f++) {
            int idx = tid + f * 256;
            int row = idx >> 5, nq = (idx & 31) * 4;
            Br[f] = *(const float4*)(W + (size_t)(sk + row) * N + n0 + nq);
        }
    };
    auto sts = [&](int i, int buf) {
        int r = i >> 5;
        bool alo = (r == 2), blo = (r == 1);
        #pragma unroll
        for (int f = 0; f < 4; f++) {
            int row = arow + f * 32;
            __nv_bfloat162 p0, p1;
            p0.x = bfpart(Ar[f].x, alo); p0.y = bfpart(Ar[f].y, alo);
            p1.x = bfpart(Ar[f].z, alo); p1.y = bfpart(Ar[f].w, alo);
            uint2 u = make_uint2(*(uint32_t*)&p0, *(uint32_t*)&p1);
            *(uint2*)&As[buf][row][akq] = u;
        }
        #pragma unroll
        for (int f = 0; f < 4; f++) {
            int idx = tid + f * 256;
            int row = idx >> 5, nq = (idx & 31) * 4;
            __nv_bfloat162 p0, p1;
            p0.x = bfpart(Br[f].x, blo); p0.y = bfpart(Br[f].y, blo);
            p1.x = bfpart(Br[f].z, blo); p1.y = bfpart(Br[f].w, blo);
            uint2 u = make_uint2(*(uint32_t*)&p0, *(uint32_t*)&p1);
            *(uint2*)&Bs[buf][row][nq] = u;
        }
    };

    ldg(0); sts(0, 0);
    __syncthreads();

    int buf = 0;
    for (int i = 0; i < 96; i++) {
        if (i + 1 < 96) ldg(i + 1);

        #pragma unroll
        for (int ks = 0; ks < 2; ks++) {
            const int k0 = ks * 16;
            uint32_t a[2][4], bb[4][4];
            #pragma unroll
            for (int mt = 0; mt < 2; mt++) {
                uint32_t sa = (uint32_t)__cvta_generic_to_shared(
                    &As[buf][wm + mt * 16 + (lane & 15)][k0 + (lane >> 4) * 8]);
                asm volatile("ldmatrix.sync.aligned.m8n8.x4.shared.b16 {%0,%1,%2,%3}, [%4];"
                    : "=r"(a[mt][0]), "=r"(a[mt][1]), "=r"(a[mt][2]), "=r"(a[mt][3])
                    : "r"(sa));
            }
            #pragma unroll
            for (int np = 0; np < 4; np++) {
                uint32_t sb = (uint32_t)__cvta_generic_to_shared(
                    &Bs[buf][k0 + (lane & 15)][wn + np * 16 + (lane >> 4) * 8]);
                asm volatile("ldmatrix.sync.aligned.m8n8.x4.trans.shared.b16 {%0,%1,%2,%3}, [%4];"
                    : "=r"(bb[np][0]), "=r"(bb[np][1]), "=r"(bb[np][2]), "=r"(bb[np][3])
                    : "r"(sb));
            }
            #pragma unroll
            for (int mt = 0; mt < 2; mt++)
                #pragma unroll
                for (int nt = 0; nt < 8; nt++) {
                    uint32_t b0 = bb[nt >> 1][(nt & 1) * 2];
                    uint32_t b1 = bb[nt >> 1][(nt & 1) * 2 + 1];
                    asm volatile(
                        "mma.sync.aligned.m16n8k16.row.col.f32.bf16.bf16.f32 "
                        "{%0,%1,%2,%3},{%4,%5,%6,%7},{%8,%9},{%0,%1,%2,%3};"
                        : "+f"(acc[mt][nt][0]), "+f"(acc[mt][nt][1]),
                          "+f"(acc[mt][nt][2]), "+f"(acc[mt][nt][3])
                        : "r"(a[mt][0]), "r"(a[mt][1]), "r"(a[mt][2]), "r"(a[mt][3]),
                          "r"(b0), "r"(b1));
                }
        }

        if (i + 1 < 96) sts(i + 1, buf ^ 1);
        __syncthreads();
        buf ^= 1;
    }

    // epilogue
    #pragma unroll
    for (int mt = 0; mt < 2; mt++) {
        #pragma unroll
        for (int nt = 0; nt < 8; nt++) {
            int row = m0 + wm + mt * 16 + (lane >> 2);
            int col = n0 + wn + nt * 8 + (lane & 3) * 2;
            float b0 = bias[col], b1 = bias[col + 1];
            float2 o0 = make_float2(acc[mt][nt][0] + b0, acc[mt][nt][1] + b1);
            float2 o1 = make_float2(acc[mt][nt][2] + b0, acc[mt][nt][3] + b1);
            *(float2*)(out + (size_t)row * N + col) = o0;
            *(float2*)(out + (size_t)(row + 8) * N + col) = o1;
        }
    }
}

// ---------------- Kernel 2: lr2 ----------------
__global__ __launch_bounds__(256) void lr2_kernel(const float* __restrict__ LR_Q)
{
    __shared__ float LQ[64][64];
    __shared__ float Ks[64][65];
    const int bh = blockIdx.y;
    const int b = bh >> 4, h = bh & (H_ - 1);
    const int s0 = blockIdx.x * 64;
    const int tid = threadIdx.x;

    for (int it = 0; it < 16; it++) {
        int f = it * 256 + tid;
        LQ[f >> 6][f & 63] = LR_Q[(size_t)(h * 64 + (f >> 6)) * 64 + (f & 63)];
    }
    for (int it = 0; it < 16; it++) {
        int f = it * 256 + tid;
        Ks[f >> 6][f & 63] =
            g_qkv[(size_t)(b * T_ + s0 + (f >> 6)) * 3072 + 1024 + h * 64 + (f & 63)];
    }
    __syncthreads();

    const int s = tid & 63;
    const int g = tid >> 6;
    float acc[16];
    #pragma unroll
    for (int nn = 0; nn < 16; nn++) acc[nn] = 0.0f;
    for (int d = 0; d < 64; d++) {
        float kv = Ks[s][d];
        #pragma unroll
        for (int nn = 0; nn < 16; nn++) acc[nn] += LQ[g * 16 + nn][d] * kv;
    }
    #pragma unroll
    for (int nn = 0; nn < 16; nn++)
        g_lr2[(size_t)(bh * 64 + g * 16 + nn) * T_ + s0 + s] = acc[nn] * 0.125f;
}

// ---------------- Kernel 3: fused attention (as R6; strides for g_qkv) ----------------
struct __align__(16) AttSmem {
    float qT[64][68];
    float kT[64][68];
    float v[64][68];
    float lr2s[64][65];
    float lr1[64][65];
    float qr[64][36];
    float rvD[33][68];
    float rv0[64];
    float relw[64];
};

__global__ void __launch_bounds__(256, 2) attn_kernel(
    const int* __restrict__ rel, const float* __restrict__ tds,
    const float* __restrict__ LR_K, const int* __restrict__ LR_map,
    const float* __restrict__ rel_w_emb, const float* __restrict__ rel_k_emb,
    const float* __restrict__ rel_v_emb)
{
    extern __shared__ char smem_raw[];
    AttSmem& sm = *reinterpret_cast<AttSmem*>(smem_raw);

    const int bid = blockIdx.x;
    const int qt = 15 - (bid >> 6);
    const int bh = bid & 63;
    const int t0 = qt * 64;
    const int b = bh >> 4, h = bh & 15;
    const int tid = threadIdx.x;
    const int lane = tid & 31, w = tid >> 5;
    const int rg = lane >> 3, kg = lane & 7;
    const int lrow0 = w * 8 + rg * 2;

    const float* qbase = g_qkv + (size_t)b * T_ * 3072 + h * 64;
    const float* kbase = qbase + 1024;
    const float* vbase = qbase + 2048;
    const float* lr2base = g_lr2 + (size_t)bh * NLOC_ * T_;
    const int* relbase = rel + (size_t)b * T_ * T_;
    const int* lmbase = LR_map + (size_t)b * T_ * T_;
    const float* tdsbase = tds + (size_t)bh * T_ * T_;

    for (int f = tid; f < 1024; f += 256) {
        int row = f >> 4, dq = (f & 15) * 4;
        float4 qv = *(const float4*)(qbase + (size_t)(t0 + row) * 3072 + dq);
        sm.qT[dq+0][row] = qv.x; sm.qT[dq+1][row] = qv.y;
        sm.qT[dq+2][row] = qv.z; sm.qT[dq+3][row] = qv.w;
    }
    if (tid < 64) { sm.relw[tid] = rel_w_emb[tid * H_ + h]; sm.rv0[tid] = rel_v_emb[tid]; }
    for (int f = tid; f < 33 * 64; f += 256) {
        int id = f >> 6, d = f & 63;
        int pd = ((d & 4) << 3) + ((d >> 3) << 2) + (d & 3);
        sm.rvD[id][pd] = rel_v_emb[id * 64 + d] - rel_v_emb[d];
    }
    __syncthreads();

    for (int task = tid; task < 33 * 64; task += 256) {
        int id = task >> 6, lr = task & 63;
        const float* rk = rel_k_emb + id * 64;
        float a = 0.0f;
        #pragma unroll 8
        for (int d = 0; d < 64; d++) a += sm.qT[d][lr] * rk[d];
        sm.qr[lr][id] = a;
    }
    for (int task = tid; task < 64 * 64; task += 256) {
        int n = task >> 6, lr = task & 63;
        const float* lk = LR_K + (size_t)(h * 64 + n) * 64;
        float a = 0.0f;
        #pragma unroll 8
        for (int d = 0; d < 64; d++) a += sm.qT[d][lr] * lk[d];
        sm.lr1[lr][n] = a * 0.125f;
    }
    __syncthreads();

    float qr0[2] = { sm.qr[lrow0][0], sm.qr[lrow0 + 1][0] };
    float m_[2] = { -1e30f, -1e30f }, l_[2] = { 0.0f, 0.0f };
    float oacc[2][8];
    #pragma unroll
    for (int r = 0; r < 2; r++)
        #pragma unroll
        for (int j = 0; j < 8; j++) oacc[r][j] = 0.0f;

    const int nchunk = qt + 1;
    for (int c = 0; c < nchunk; c++) {
        const int s0c = c * 64;
        __syncthreads();
        for (int f = tid; f < 1024; f += 256) {
            int s = f >> 4, dq = (f & 15) * 4;
            float4 kv = *(const float4*)(kbase + (size_t)(s0c + s) * 3072 + dq);
            int ps = ((s & 4) << 3) + ((s >> 3) << 2) + (s & 3);
            sm.kT[dq+0][ps] = kv.x; sm.kT[dq+1][ps] = kv.y;
            sm.kT[dq+2][ps] = kv.z; sm.kT[dq+3][ps] = kv.w;
            int pd = ((dq & 4) << 3) + ((dq >> 3) << 2);
            *(float4*)&sm.v[s][pd] = *(const float4*)(vbase + (size_t)(s0c + s) * 3072 + dq);
            float4 l4 = *(const float4*)(lr2base + (size_t)s * T_ + s0c + dq);
            sm.lr2s[s][dq+0] = l4.x; sm.lr2s[s][dq+1] = l4.y;
            sm.lr2s[s][dq+2] = l4.z; sm.lr2s[s][dq+3] = l4.w;
        }
        __syncthreads();

        const bool diag = (c + 1 == nchunk);
        const bool far = (s0c + 96 <= t0 + w * 8);

        float sc[2][8];
        #pragma unroll
        for (int r = 0; r < 2; r++)
            #pragma unroll
            for (int j = 0; j < 8; j++) sc[r][j] = 0.0f;
        #pragma unroll 4
        for (int d = 0; d < 64; d++) {
            float2 qv = *(const float2*)&sm.qT[d][lrow0];
            float4 k0 = *(const float4*)&sm.kT[d][kg * 4];
            float4 k1 = *(const float4*)&sm.kT[d][32 + kg * 4];
            sc[0][0] = fmaf(qv.x, k0.x, sc[0][0]); sc[1][0] = fmaf(qv.y, k0.x, sc[1][0]);
            sc[0][1] = fmaf(qv.x, k0.y, sc[0][1]); sc[1][1] = fmaf(qv.y, k0.y, sc[1][1]);
            sc[0][2] = fmaf(qv.x, k0.z, sc[0][2]); sc[1][2] = fmaf(qv.y, k0.z, sc[1][2]);
            sc[0][3] = fmaf(qv.x, k0.w, sc[0][3]); sc[1][3] = fmaf(qv.y, k0.w, sc[1][3]);
            sc[0][4] = fmaf(qv.x, k1.x, sc[0][4]); sc[1][4] = fmaf(qv.y, k1.x, sc[1][4]);
            sc[0][5] = fmaf(qv.x, k1.y, sc[0][5]); sc[1][5] = fmaf(qv.y, k1.y, sc[1][5]);
            sc[0][6] = fmaf(qv.x, k1.z, sc[0][6]); sc[1][6] = fmaf(qv.y, k1.z, sc[1][6]);
            sc[0][7] = fmaf(qv.x, k1.w, sc[0][7]); sc[1][7] = fmaf(qv.y, k1.w, sc[1][7]);
        }

        #pragma unroll
        for (int r = 0; r < 2; r++) {
            const int lr = lrow0 + r;
            const int tr = t0 + lr;
            const size_t off = (size_t)tr * T_ + s0c + kg * 8;
            float wv[8];
            {
                int4 ra = *(const int4*)(relbase + off);
                int4 la = *(const int4*)(lmbase + off);
                float4 ta = *(const float4*)(tdsbase + off);
                int rl[4] = {ra.x, ra.y, ra.z, ra.w};
                int lm[4] = {la.x, la.y, la.z, la.w};
                float td[4] = {ta.x, ta.y, ta.z, ta.w};
                #pragma unroll
                for (int j = 0; j < 4; j++) {
                    int sl = kg * 8 + j;
                    float qadd;
                    if (far) qadd = qr0[r];
                    else {
                        int id = s0c + sl - tr + 32;
                        id = id < 0 ? 0 : (id > 32 ? 32 : id);
                        qadd = sm.qr[lr][id];
                    }
                    float x = fmaf((sc[r][j] + qadd) * 0.125f, sm.relw[rl[j]], td[j]);
                    x += sm.lr1[lr][lm[j]] + sm.lr2s[lm[j]][sl];
                    wv[j] = x * 0.70710678118f;
                    if (diag && sl > lr) wv[j] = -1e30f;
                }
            }
            {
                int4 ra = *(const int4*)(relbase + off + 4);
                int4 la = *(const int4*)(lmbase + off + 4);
                float4 ta = *(const float4*)(tdsbase + off + 4);
                int rl[4] = {ra.x, ra.y, ra.z, ra.w};
                int lm[4] = {la.x, la.y, la.z, la.w};
                float td[4] = {ta.x, ta.y, ta.z, ta.w};
                #pragma unroll
                for (int j = 0; j < 4; j++) {
                    int sl = kg * 8 + 4 + j;
                    float qadd;
                    if (far) qadd = qr0[r];
                    else {
                        int id = s0c + sl - tr + 32;
                        id = id < 0 ? 0 : (id > 32 ? 32 : id);
                        qadd = sm.qr[lr][id];
                    }
                    float x = fmaf((sc[r][4+j] + qadd) * 0.125f, sm.relw[rl[j]], td[j]);
                    x += sm.lr1[lr][lm[j]] + sm.lr2s[lm[j]][sl];
                    wv[4+j] = x * 0.70710678118f;
                    if (diag && sl > lr) wv[4+j] = -1e30f;
                }
            }
            float tmax = wv[0];
            #pragma unroll
            for (int j = 1; j < 8; j++) tmax = fmaxf(tmax, wv[j]);
            tmax = fmaxf(tmax, __shfl_xor_sync(0xffffffffu, tmax, 1));
            tmax = fmaxf(tmax, __shfl_xor_sync(0xffffffffu, tmax, 2));
            tmax = fmaxf(tmax, __shfl_xor_sync(0xffffffffu, tmax, 4));
            float mn = fmaxf(m_[r], tmax);
            float scale = __expf(m_[r] - mn);
            float psum = 0.0f;
            #pragma unroll
            for (int j = 0; j < 8; j++) { sc[r][j] = __expf(wv[j] - mn); psum += sc[r][j]; }
            psum += __shfl_xor_sync(0xffffffffu, psum, 1);
            psum += __shfl_xor_sync(0xffffffffu, psum, 2);
            psum += __shfl_xor_sync(0xffffffffu, psum, 4);
            l_[r] = l_[r] * scale + psum;
            m_[r] = mn;
            #pragma unroll
            for (int j = 0; j < 8; j++) oacc[r][j] *= scale;
        }

        if (far) {
            for (int g = 0; g < 8; g++) {
                #pragma unroll
                for (int j = 0; j < 8; j++) {
                    int sl = g * 8 + j;
                    float4 v0 = *(const float4*)&sm.v[sl][kg * 4];
                    float4 v1 = *(const float4*)&sm.v[sl][32 + kg * 4];
                    int src = rg * 8 + g;
                    float p0 = __shfl_sync(0xffffffffu, sc[0][j], src);
                    float p1 = __shfl_sync(0xffffffffu, sc[1][j], src);
                    oacc[0][0] = fmaf(p0, v0.x, oacc[0][0]); oacc[1][0] = fmaf(p1, v0.x, oacc[1][0]);
                    oacc[0][1] = fmaf(p0, v0.y, oacc[0][1]); oacc[1][1] = fmaf(p1, v0.y, oacc[1][1]);
                    oacc[0][2] = fmaf(p0, v0.z, oacc[0][2]); oacc[1][2] = fmaf(p1, v0.z, oacc[1][2]);
                    oacc[0][3] = fmaf(p0, v0.w, oacc[0][3]); oacc[1][3] = fmaf(p1, v0.w, oacc[1][3]);
                    oacc[0][4] = fmaf(p0, v1.x, oacc[0][4]); oacc[1][4] = fmaf(p1, v1.x, oacc[1][4]);
                    oacc[0][5] = fmaf(p0, v1.y, oacc[0][5]); oacc[1][5] = fmaf(p1, v1.y, oacc[1][5]);
                    oacc[0][6] = fmaf(p0, v1.z, oacc[0][6]); oacc[1][6] = fmaf(p1, v1.z, oacc[1][6]);
                    oacc[0][7] = fmaf(p0, v1.w, oacc[0][7]); oacc[1][7] = fmaf(p1, v1.w, oacc[1][7]);
                }
            }
        } else {
            for (int g = 0; g < 8; g++) {
                #pragma unroll
                for (int j = 0; j < 8; j++) {
                    int sl = g * 8 + j;
                    float4 v0 = *(const float4*)&sm.v[sl][kg * 4];
                    float4 v1 = *(const float4*)&sm.v[sl][32 + kg * 4];
                    int src = rg * 8 + g;
                    float p0 = __shfl_sync(0xffffffffu, sc[0][j], src);
                    float p1 = __shfl_sync(0xffffffffu, sc[1][j], src);
                    int id0 = s0c + sl - (t0 + lrow0) + 32;
                    id0 = id0 < 0 ? 0 : (id0 > 32 ? 32 : id0);
                    int id1 = s0c + sl - (t0 + lrow0 + 1) + 32;
                    id1 = id1 < 0 ? 0 : (id1 > 32 ? 32 : id1);
                    float4 w00 = *(const float4*)&sm.rvD[id0][kg * 4];
                    float4 w01 = *(const float4*)&sm.rvD[id0][32 + kg * 4];
                    float4 w10 = *(const float4*)&sm.rvD[id1][kg * 4];
                    float4 w11 = *(const float4*)&sm.rvD[id1][32 + kg * 4];
                    oacc[0][0] = fmaf(p0, v0.x + w00.x, oacc[0][0]); oacc[1][0] = fmaf(p1, v0.x + w10.x, oacc[1][0]);
                    oacc[0][1] = fmaf(p0, v0.y + w00.y, oacc[0][1]); oacc[1][1] = fmaf(p1, v0.y + w10.y, oacc[1][1]);
                    oacc[0][2] = fmaf(p0, v0.z + w00.z, oacc[0][2]); oacc[1][2] = fmaf(p1, v0.z + w10.z, oacc[1][2]);
                    oacc[0][3] = fmaf(p0, v0.w + w00.w, oacc[0][3]); oacc[1][3] = fmaf(p1, v0.w + w10.w, oacc[1][3]);
                    oacc[0][4] = fmaf(p0, v1.x + w01.x, oacc[0][4]); oacc[1][4] = fmaf(p1, v1.x + w11.x, oacc[1][4]);
                    oacc[0][5] = fmaf(p0, v1.y + w01.y, oacc[0][5]); oacc[1][5] = fmaf(p1, v1.y + w11.y, oacc[1][5]);
                    oacc[0][6] = fmaf(p0, v1.z + w01.z, oacc[0][6]); oacc[1][6] = fmaf(p1, v1.z + w11.z, oacc[1][6]);
                    oacc[0][7] = fmaf(p0, v1.w + w01.w, oacc[0][7]); oacc[1][7] = fmaf(p1, v1.w + w11.w, oacc[1][7]);
                }
            }
        }
    }

    float4 r0 = *(const float4*)&sm.rv0[kg * 8];
    float4 r1 = *(const float4*)&sm.rv0[kg * 8 + 4];
    #pragma unroll
    for (int r = 0; r < 2; r++) {
        int tr = t0 + lrow0 + r;
        float invl = 1.0f / l_[r];
        float* orow = g_att + (size_t)(b * T_ + tr) * NX_ + h * 64 + kg * 8;
        float4 o0 = make_float4(oacc[r][0]*invl + r0.x, oacc[r][1]*invl + r0.y,
                                oacc[r][2]*invl + r0.z, oacc[r][3]*invl + r0.w);
        float4 o1 = make_float4(oacc[r][4]*invl + r1.x, oacc[r][5]*invl + r1.y,
                                oacc[r][6]*invl + r1.z, oacc[r][7]*invl + r1.w);
        *(float4*)(orow) = o0;
        *(float4*)(orow + 4) = o1;
    }
}

// ---------------- launch ----------------
extern "C" void kernel_launch(void* const* d_in, const int* in_sizes, int n_in,
                              void* d_out, int out_size)
{
    const float* x          = (const float*)d_in[0];
    const int*   rel        = (const int*)  d_in[1];
    const float* tds        = (const float*)d_in[2];
    const float* LR_Q       = (const float*)d_in[3];
    const float* LR_K       = (const float*)d_in[4];
    const int*   LR_map     = (const int*)  d_in[5];
    const float* c_attn_w   = (const float*)d_in[6];
    const float* c_attn_b   = (const float*)d_in[7];
    const float* c_proj_w   = (const float*)d_in[8];
    const float* c_proj_b   = (const float*)d_in[9];
    const float* rel_w_emb  = (const float*)d_in[10];
    const float* rel_k_emb  = (const float*)d_in[11];
    const float* rel_v_emb  = (const float*)d_in[12];
    float* out = (float*)d_out;

    cudaFuncSetAttribute(attn_kernel, cudaFuncAttributeMaxDynamicSharedMemorySize,
                         (int)sizeof(AttSmem));

    float* qkv_buf; cudaGetSymbolAddress((void**)&qkv_buf, g_qkv);
    float* att_buf; cudaGetSymbolAddress((void**)&att_buf, g_att);

    gemm_bf16x3<<<dim3(24, 32), 256>>>(x, c_attn_w, c_attn_b, qkv_buf, 3072);
    lr2_kernel<<<dim3(16, 64), 256>>>(LR_Q);
    attn_kernel<<<1024, 256, sizeof(AttSmem)>>>(
        rel, tds, LR_K, LR_map, rel_w_emb, rel_k_emb, rel_v_emb);
    gemm_bf16x3<<<dim3(8, 32), 256>>>(att_buf, c_proj_w, c_proj_b, out, 1024);
}

// round 8
// speedup vs baseline: 4.8129x; 1.1746x over previous
#include <cuda_runtime.h>
#include <cuda_bf16.h>
#include <stdint.h>

#define B_ 4
#define T_ 1024
#define NX_ 1024
#define H_ 16
#define D_ 64
#define KMAX_ 32
#define NLOC_ 64

// scratch: pre-split bf16 planes ([0]=hi, [1]=lo) + fp32 intermediates
__device__ __nv_bfloat16 g_xs[2][B_*T_*NX_];
__device__ __nv_bfloat16 g_w1s[2][NX_*3*NX_];
__device__ __nv_bfloat16 g_w2s[2][NX_*NX_];
__device__ __nv_bfloat16 g_atts[2][B_*T_*NX_];
__device__ float g_qkv[B_*T_*3*NX_];
__device__ float g_lr2[B_*H_*NLOC_*T_];

// ---------------- split: fp32 -> (hi, lo) bf16 planes ----------------
__global__ __launch_bounds__(256) void split_kernel(
    const float* __restrict__ in, __nv_bfloat16* __restrict__ hi,
    __nv_bfloat16* __restrict__ lo, int n4)
{
    int i = blockIdx.x * 256 + threadIdx.x;
    if (i >= n4) return;
    float4 v = *(const float4*)(in + i * 4);
    __nv_bfloat16 h0 = __float2bfloat16(v.x), h1 = __float2bfloat16(v.y);
    __nv_bfloat16 h2 = __float2bfloat16(v.z), h3 = __float2bfloat16(v.w);
    __nv_bfloat16 l0 = __float2bfloat16(v.x - __bfloat162float(h0));
    __nv_bfloat16 l1 = __float2bfloat16(v.y - __bfloat162float(h1));
    __nv_bfloat16 l2 = __float2bfloat16(v.z - __bfloat162float(h2));
    __nv_bfloat16 l3 = __float2bfloat16(v.w - __bfloat162float(h3));
    __nv_bfloat162 hh0; hh0.x = h0; hh0.y = h1;
    __nv_bfloat162 hh1; hh1.x = h2; hh1.y = h3;
    __nv_bfloat162 ll0; ll0.x = l0; ll0.y = l1;
    __nv_bfloat162 ll1; ll1.x = l2; ll1.y = l3;
    *(uint2*)(hi + i * 4) = make_uint2(*(uint32_t*)&hh0, *(uint32_t*)&hh1);
    *(uint2*)(lo + i * 4) = make_uint2(*(uint32_t*)&ll0, *(uint32_t*)&ll1);
}

// ---------------- bf16x3 tensor-core GEMM on pre-split planes ----------------
// out[M,N] = A @ W + bias; A planes [2][4096*1024], W planes [2][1024*N].
// pass r=0: Ah*Wh, r=1: Ah*Wl, r=2: Al*Wh. CTA 128x128, 8 warps.
__global__ __launch_bounds__(256) void gemm_bf16x3s(
    const __nv_bfloat16* __restrict__ A, const __nv_bfloat16* __restrict__ W,
    const float* __restrict__ bias, float* __restrict__ out, int N)
{
    __shared__ __nv_bfloat16 As[2][128][40];
    __shared__ __nv_bfloat16 Bs[2][32][136];
    const int n0 = blockIdx.x * 128;
    const int m0 = blockIdx.y * 128;
    const int tid = threadIdx.x;
    const int lane = tid & 31, w = tid >> 5;
    const int wm = (w >> 1) * 32, wn = (w & 1) * 64;
    const size_t ASTRIDE = (size_t)4096 * 1024;
    const size_t WSTRIDE = (size_t)1024 * N;

    float acc[2][8][4];
    #pragma unroll
    for (int mt = 0; mt < 2; mt++)
        #pragma unroll
        for (int nt = 0; nt < 8; nt++)
            #pragma unroll
            for (int i = 0; i < 4; i++) acc[mt][nt][i] = 0.0f;

    // A tile 128x32: 512 8-elem chunks, 2/thread. B tile 32x128: same.
    const int ar0 = tid >> 2, ac0 = (tid & 3) * 8;
    const int br0 = tid >> 4, bc0 = (tid & 15) * 8;
    uint4 Ar[2], Br[2];

    auto ldg = [&](int i) {
        int r = i >> 5, sk = (i & 31) * 32;
        const __nv_bfloat16* Ap = A + (r == 2 ? ASTRIDE : 0);
        const __nv_bfloat16* Wp = W + (r == 1 ? WSTRIDE : 0);
        Ar[0] = *(const uint4*)(Ap + (size_t)(m0 + ar0) * 1024 + sk + ac0);
        Ar[1] = *(const uint4*)(Ap + (size_t)(m0 + ar0 + 64) * 1024 + sk + ac0);
        Br[0] = *(const uint4*)(Wp + (size_t)(sk + br0) * N + n0 + bc0);
        Br[1] = *(const uint4*)(Wp + (size_t)(sk + br0 + 16) * N + n0 + bc0);
    };
    auto sts = [&](int buf) {
        *(uint2*)&As[buf][ar0][ac0]      = make_uint2(Ar[0].x, Ar[0].y);
        *(uint2*)&As[buf][ar0][ac0 + 4]  = make_uint2(Ar[0].z, Ar[0].w);
        *(uint2*)&As[buf][ar0 + 64][ac0]     = make_uint2(Ar[1].x, Ar[1].y);
        *(uint2*)&As[buf][ar0 + 64][ac0 + 4] = make_uint2(Ar[1].z, Ar[1].w);
        *(uint4*)&Bs[buf][br0][bc0]      = Br[0];
        *(uint4*)&Bs[buf][br0 + 16][bc0] = Br[1];
    };

    ldg(0); sts(0);
    __syncthreads();

    int buf = 0;
    for (int i = 0; i < 96; i++) {
        if (i + 1 < 96) ldg(i + 1);

        #pragma unroll
        for (int ks = 0; ks < 2; ks++) {
            const int k0 = ks * 16;
            uint32_t a[2][4], bb[4][4];
            #pragma unroll
            for (int mt = 0; mt < 2; mt++) {
                uint32_t sa = (uint32_t)__cvta_generic_to_shared(
                    &As[buf][wm + mt * 16 + (lane & 15)][k0 + (lane >> 4) * 8]);
                asm volatile("ldmatrix.sync.aligned.m8n8.x4.shared.b16 {%0,%1,%2,%3}, [%4];"
                    : "=r"(a[mt][0]), "=r"(a[mt][1]), "=r"(a[mt][2]), "=r"(a[mt][3])
                    : "r"(sa));
            }
            #pragma unroll
            for (int np = 0; np < 4; np++) {
                uint32_t sb = (uint32_t)__cvta_generic_to_shared(
                    &Bs[buf][k0 + (lane & 15)][wn + np * 16 + (lane >> 4) * 8]);
                asm volatile("ldmatrix.sync.aligned.m8n8.x4.trans.shared.b16 {%0,%1,%2,%3}, [%4];"
                    : "=r"(bb[np][0]), "=r"(bb[np][1]), "=r"(bb[np][2]), "=r"(bb[np][3])
                    : "r"(sb));
            }
            #pragma unroll
            for (int mt = 0; mt < 2; mt++)
                #pragma unroll
                for (int nt = 0; nt < 8; nt++) {
                    uint32_t b0 = bb[nt >> 1][(nt & 1) * 2];
                    uint32_t b1 = bb[nt >> 1][(nt & 1) * 2 + 1];
                    asm volatile(
                        "mma.sync.aligned.m16n8k16.row.col.f32.bf16.bf16.f32 "
                        "{%0,%1,%2,%3},{%4,%5,%6,%7},{%8,%9},{%0,%1,%2,%3};"
                        : "+f"(acc[mt][nt][0]), "+f"(acc[mt][nt][1]),
                          "+f"(acc[mt][nt][2]), "+f"(acc[mt][nt][3])
                        : "r"(a[mt][0]), "r"(a[mt][1]), "r"(a[mt][2]), "r"(a[mt][3]),
                          "r"(b0), "r"(b1));
                }
        }

        if (i + 1 < 96) sts(buf ^ 1);
        __syncthreads();
        buf ^= 1;
    }

    #pragma unroll
    for (int mt = 0; mt < 2; mt++) {
        #pragma unroll
        for (int nt = 0; nt < 8; nt++) {
            int row = m0 + wm + mt * 16 + (lane >> 2);
            int col = n0 + wn + nt * 8 + (lane & 3) * 2;
            float b0 = bias[col], b1 = bias[col + 1];
            float2 o0 = make_float2(acc[mt][nt][0] + b0, acc[mt][nt][1] + b1);
            float2 o1 = make_float2(acc[mt][nt][2] + b0, acc[mt][nt][3] + b1);
            *(float2*)(out + (size_t)row * N + col) = o0;
            *(float2*)(out + (size_t)(row + 8) * N + col) = o1;
        }
    }
}

// ---------------- lr2 ----------------
__global__ __launch_bounds__(256) void lr2_kernel(const float* __restrict__ LR_Q)
{
    __shared__ float LQ[64][64];
    __shared__ float Ks[64][65];
    const int bh = blockIdx.y;
    const int b = bh >> 4, h = bh & (H_ - 1);
    const int s0 = blockIdx.x * 64;
    const int tid = threadIdx.x;

    for (int it = 0; it < 16; it++) {
        int f = it * 256 + tid;
        LQ[f >> 6][f & 63] = LR_Q[(size_t)(h * 64 + (f >> 6)) * 64 + (f & 63)];
    }
    for (int it = 0; it < 16; it++) {
        int f = it * 256 + tid;
        Ks[f >> 6][f & 63] =
            g_qkv[(size_t)(b * T_ + s0 + (f >> 6)) * 3072 + 1024 + h * 64 + (f & 63)];
    }
    __syncthreads();

    const int s = tid & 63;
    const int g = tid >> 6;
    float acc[16];
    #pragma unroll
    for (int nn = 0; nn < 16; nn++) acc[nn] = 0.0f;
    for (int d = 0; d < 64; d++) {
        float kv = Ks[s][d];
        #pragma unroll
        for (int nn = 0; nn < 16; nn++) acc[nn] += LQ[g * 16 + nn][d] * kv;
    }
    #pragma unroll
    for (int nn = 0; nn < 16; nn++)
        g_lr2[(size_t)(bh * 64 + g * 16 + nn) * T_ + s0 + s] = acc[nn] * 0.125f;
}

// ---------------- fused attention (R6 structure; bf16-split epilogue) ----------------
struct __align__(16) AttSmem {
    float qT[64][68];
    float kT[64][68];
    float v[64][68];
    float lr2s[64][65];
    float lr1[64][65];
    float qr[64][36];
    float rvD[33][68];
    float rv0[64];
    float relw[64];
};

__global__ void __launch_bounds__(256, 2) attn_kernel(
    const int* __restrict__ rel, const float* __restrict__ tds,
    const float* __restrict__ LR_K, const int* __restrict__ LR_map,
    const float* __restrict__ rel_w_emb, const float* __restrict__ rel_k_emb,
    const float* __restrict__ rel_v_emb)
{
    extern __shared__ char smem_raw[];
    AttSmem& sm = *reinterpret_cast<AttSmem*>(smem_raw);

    const int bid = blockIdx.x;
    const int qt = 15 - (bid >> 6);
    const int bh = bid & 63;
    const int t0 = qt * 64;
    const int b = bh >> 4, h = bh & 15;
    const int tid = threadIdx.x;
    const int lane = tid & 31, w = tid >> 5;
    const int rg = lane >> 3, kg = lane & 7;
    const int lrow0 = w * 8 + rg * 2;

    const float* qbase = g_qkv + (size_t)b * T_ * 3072 + h * 64;
    const float* kbase = qbase + 1024;
    const float* vbase = qbase + 2048;
    const float* lr2base = g_lr2 + (size_t)bh * NLOC_ * T_;
    const int* relbase = rel + (size_t)b * T_ * T_;
    const int* lmbase = LR_map + (size_t)b * T_ * T_;
    const float* tdsbase = tds + (size_t)bh * T_ * T_;

    for (int f = tid; f < 1024; f += 256) {
        int row = f >> 4, dq = (f & 15) * 4;
        float4 qv = *(const float4*)(qbase + (size_t)(t0 + row) * 3072 + dq);
        sm.qT[dq+0][row] = qv.x; sm.qT[dq+1][row] = qv.y;
        sm.qT[dq+2][row] = qv.z; sm.qT[dq+3][row] = qv.w;
    }
    if (tid < 64) { sm.relw[tid] = rel_w_emb[tid * H_ + h]; sm.rv0[tid] = rel_v_emb[tid]; }
    for (int f = tid; f < 33 * 64; f += 256) {
        int id = f >> 6, d = f & 63;
        int pd = ((d & 4) << 3) + ((d >> 3) << 2) + (d & 3);
        sm.rvD[id][pd] = rel_v_emb[id * 64 + d] - rel_v_emb[d];
    }
    __syncthreads();

    for (int task = tid; task < 33 * 64; task += 256) {
        int id = task >> 6, lr = task & 63;
        const float* rk = rel_k_emb + id * 64;
        float a = 0.0f;
        #pragma unroll 8
        for (int d = 0; d < 64; d++) a += sm.qT[d][lr] * rk[d];
        sm.qr[lr][id] = a;
    }
    for (int task = tid; task < 64 * 64; task += 256) {
        int n = task >> 6, lr = task & 63;
        const float* lk = LR_K + (size_t)(h * 64 + n) * 64;
        float a = 0.0f;
        #pragma unroll 8
        for (int d = 0; d < 64; d++) a += sm.qT[d][lr] * lk[d];
        sm.lr1[lr][n] = a * 0.125f;
    }
    __syncthreads();

    float qr0[2] = { sm.qr[lrow0][0], sm.qr[lrow0 + 1][0] };
    float m_[2] = { -1e30f, -1e30f }, l_[2] = { 0.0f, 0.0f };
    float oacc[2][8];
    #pragma unroll
    for (int r = 0; r < 2; r++)
        #pragma unroll
        for (int j = 0; j < 8; j++) oacc[r][j] = 0.0f;

    const int nchunk = qt + 1;
    for (int c = 0; c < nchunk; c++) {
        const int s0c = c * 64;
        __syncthreads();
        for (int f = tid; f < 1024; f += 256) {
            int s = f >> 4, dq = (f & 15) * 4;
            float4 kv = *(const float4*)(kbase + (size_t)(s0c + s) * 3072 + dq);
            int ps = ((s & 4) << 3) + ((s >> 3) << 2) + (s & 3);
            sm.kT[dq+0][ps] = kv.x; sm.kT[dq+1][ps] = kv.y;
            sm.kT[dq+2][ps] = kv.z; sm.kT[dq+3][ps] = kv.w;
            int pd = ((dq & 4) << 3) + ((dq >> 3) << 2);
            *(float4*)&sm.v[s][pd] = *(const float4*)(vbase + (size_t)(s0c + s) * 3072 + dq);
            float4 l4 = *(const float4*)(lr2base + (size_t)s * T_ + s0c + dq);
            sm.lr2s[s][dq+0] = l4.x; sm.lr2s[s][dq+1] = l4.y;
            sm.lr2s[s][dq+2] = l4.z; sm.lr2s[s][dq+3] = l4.w;
        }
        __syncthreads();

        const bool diag = (c + 1 == nchunk);
        const bool far = (s0c + 96 <= t0 + w * 8);

        float sc[2][8];
        #pragma unroll
        for (int r = 0; r < 2; r++)
            #pragma unroll
            for (int j = 0; j < 8; j++) sc[r][j] = 0.0f;
        #pragma unroll 4
        for (int d = 0; d < 64; d++) {
            float2 qv = *(const float2*)&sm.qT[d][lrow0];
            float4 k0 = *(const float4*)&sm.kT[d][kg * 4];
            float4 k1 = *(const float4*)&sm.kT[d][32 + kg * 4];
            sc[0][0] = fmaf(qv.x, k0.x, sc[0][0]); sc[1][0] = fmaf(qv.y, k0.x, sc[1][0]);
            sc[0][1] = fmaf(qv.x, k0.y, sc[0][1]); sc[1][1] = fmaf(qv.y, k0.y, sc[1][1]);
            sc[0][2] = fmaf(qv.x, k0.z, sc[0][2]); sc[1][2] = fmaf(qv.y, k0.z, sc[1][2]);
            sc[0][3] = fmaf(qv.x, k0.w, sc[0][3]); sc[1][3] = fmaf(qv.y, k0.w, sc[1][3]);
            sc[0][4] = fmaf(qv.x, k1.x, sc[0][4]); sc[1][4] = fmaf(qv.y, k1.x, sc[1][4]);
            sc[0][5] = fmaf(qv.x, k1.y, sc[0][5]); sc[1][5] = fmaf(qv.y, k1.y, sc[1][5]);
            sc[0][6] = fmaf(qv.x, k1.z, sc[0][6]); sc[1][6] = fmaf(qv.y, k1.z, sc[1][6]);
            sc[0][7] = fmaf(qv.x, k1.w, sc[0][7]); sc[1][7] = fmaf(qv.y, k1.w, sc[1][7]);
        }

        #pragma unroll
        for (int r = 0; r < 2; r++) {
            const int lr = lrow0 + r;
            const int tr = t0 + lr;
            const size_t off = (size_t)tr * T_ + s0c + kg * 8;
            float wv[8];
            {
                int4 ra = *(const int4*)(relbase + off);
                int4 la = *(const int4*)(lmbase + off);
                float4 ta = *(const float4*)(tdsbase + off);
                int rl[4] = {ra.x, ra.y, ra.z, ra.w};
                int lm[4] = {la.x, la.y, la.z, la.w};
                float td[4] = {ta.x, ta.y, ta.z, ta.w};
                #pragma unroll
                for (int j = 0; j < 4; j++) {
                    int sl = kg * 8 + j;
                    float qadd;
                    if (far) qadd = qr0[r];
                    else {
                        int id = s0c + sl - tr + 32;
                        id = id < 0 ? 0 : (id > 32 ? 32 : id);
                        qadd = sm.qr[lr][id];
                    }
                    float x = fmaf((sc[r][j] + qadd) * 0.125f, sm.relw[rl[j]], td[j]);
                    x += sm.lr1[lr][lm[j]] + sm.lr2s[lm[j]][sl];
                    wv[j] = x * 0.70710678118f;
                    if (diag && sl > lr) wv[j] = -1e30f;
                }
            }
            {
                int4 ra = *(const int4*)(relbase + off + 4);
                int4 la = *(const int4*)(lmbase + off + 4);
                float4 ta = *(const float4*)(tdsbase + off + 4);
                int rl[4] = {ra.x, ra.y, ra.z, ra.w};
                int lm[4] = {la.x, la.y, la.z, la.w};
                float td[4] = {ta.x, ta.y, ta.z, ta.w};
                #pragma unroll
                for (int j = 0; j < 4; j++) {
                    int sl = kg * 8 + 4 + j;
                    float qadd;
                    if (far) qadd = qr0[r];
                    else {
                        int id = s0c + sl - tr + 32;
                        id = id < 0 ? 0 : (id > 32 ? 32 : id);
                        qadd = sm.qr[lr][id];
                    }
                    float x = fmaf((sc[r][4+j] + qadd) * 0.125f, sm.relw[rl[j]], td[j]);
                    x += sm.lr1[lr][lm[j]] + sm.lr2s[lm[j]][sl];
                    wv[4+j] = x * 0.70710678118f;
                    if (diag && sl > lr) wv[4+j] = -1e30f;
                }
            }
            float tmax = wv[0];
            #pragma unroll
            for (int j = 1; j < 8; j++) tmax = fmaxf(tmax, wv[j]);
            tmax = fmaxf(tmax, __shfl_xor_sync(0xffffffffu, tmax, 1));
            tmax = fmaxf(tmax, __shfl_xor_sync(0xffffffffu, tmax, 2));
            tmax = fmaxf(tmax, __shfl_xor_sync(0xffffffffu, tmax, 4));
            float mn = fmaxf(m_[r], tmax);
            float scale = __expf(m_[r] - mn);
            float psum = 0.0f;
            #pragma unroll
            for (int j = 0; j < 8; j++) { sc[r][j] = __expf(wv[j] - mn); psum += sc[r][j]; }
            psum += __shfl_xor_sync(0xffffffffu, psum, 1);
            psum += __shfl_xor_sync(0xffffffffu, psum, 2);
            psum += __shfl_xor_sync(0xffffffffu, psum, 4);
            l_[r] = l_[r] * scale + psum;
            m_[r] = mn;
            #pragma unroll
            for (int j = 0; j < 8; j++) oacc[r][j] *= scale;
        }

        if (far) {
            for (int g = 0; g < 8; g++) {
                #pragma unroll
                for (int j = 0; j < 8; j++) {
                    int sl = g * 8 + j;
                    float4 v0 = *(const float4*)&sm.v[sl][kg * 4];
                    float4 v1 = *(const float4*)&sm.v[sl][32 + kg * 4];
                    int src = rg * 8 + g;
                    float p0 = __shfl_sync(0xffffffffu, sc[0][j], src);
                    float p1 = __shfl_sync(0xffffffffu, sc[1][j], src);
                    oacc[0][0] = fmaf(p0, v0.x, oacc[0][0]); oacc[1][0] = fmaf(p1, v0.x, oacc[1][0]);
                    oacc[0][1] = fmaf(p0, v0.y, oacc[0][1]); oacc[1][1] = fmaf(p1, v0.y, oacc[1][1]);
                    oacc[0][2] = fmaf(p0, v0.z, oacc[0][2]); oacc[1][2] = fmaf(p1, v0.z, oacc[1][2]);
                    oacc[0][3] = fmaf(p0, v0.w, oacc[0][3]); oacc[1][3] = fmaf(p1, v0.w, oacc[1][3]);
                    oacc[0][4] = fmaf(p0, v1.x, oacc[0][4]); oacc[1][4] = fmaf(p1, v1.x, oacc[1][4]);
                    oacc[0][5] = fmaf(p0, v1.y, oacc[0][5]); oacc[1][5] = fmaf(p1, v1.y, oacc[1][5]);
                    oacc[0][6] = fmaf(p0, v1.z, oacc[0][6]); oacc[1][6] = fmaf(p1, v1.z, oacc[1][6]);
                    oacc[0][7] = fmaf(p0, v1.w, oacc[0][7]); oacc[1][7] = fmaf(p1, v1.w, oacc[1][7]);
                }
            }
        } else {
            for (int g = 0; g < 8; g++) {
                #pragma unroll
                for (int j = 0; j < 8; j++) {
                    int sl = g * 8 + j;
                    float4 v0 = *(const float4*)&sm.v[sl][kg * 4];
                    float4 v1 = *(const float4*)&sm.v[sl][32 + kg * 4];
                    int src = rg * 8 + g;
                    float p0 = __shfl_sync(0xffffffffu, sc[0][j], src);
                    float p1 = __shfl_sync(0xffffffffu, sc[1][j], src);
                    int id0 = s0c + sl - (t0 + lrow0) + 32;
                    id0 = id0 < 0 ? 0 : (id0 > 32 ? 32 : id0);
                    int id1 = s0c + sl - (t0 + lrow0 + 1) + 32;
                    id1 = id1 < 0 ? 0 : (id1 > 32 ? 32 : id1);
                    float4 w00 = *(const float4*)&sm.rvD[id0][kg * 4];
                    float4 w01 = *(const float4*)&sm.rvD[id0][32 + kg * 4];
                    float4 w10 = *(const float4*)&sm.rvD[id1][kg * 4];
                    float4 w11 = *(const float4*)&sm.rvD[id1][32 + kg * 4];
                    oacc[0][0] = fmaf(p0, v0.x + w00.x, oacc[0][0]); oacc[1][0] = fmaf(p1, v0.x + w10.x, oacc[1][0]);
                    oacc[0][1] = fmaf(p0, v0.y + w00.y, oacc[0][1]); oacc[1][1] = fmaf(p1, v0.y + w10.y, oacc[1][1]);
                    oacc[0][2] = fmaf(p0, v0.z + w00.z, oacc[0][2]); oacc[1][2] = fmaf(p1, v0.z + w10.z, oacc[1][2]);
                    oacc[0][3] = fmaf(p0, v0.w + w00.w, oacc[0][3]); oacc[1][3] = fmaf(p1, v0.w + w10.w, oacc[1][3]);
                    oacc[0][4] = fmaf(p0, v1.x + w01.x, oacc[0][4]); oacc[1][4] = fmaf(p1, v1.x + w11.x, oacc[1][4]);
                    oacc[0][5] = fmaf(p0, v1.y + w01.y, oacc[0][5]); oacc[1][5] = fmaf(p1, v1.y + w11.y, oacc[1][5]);
                    oacc[0][6] = fmaf(p0, v1.z + w01.z, oacc[0][6]); oacc[1][6] = fmaf(p1, v1.z + w11.z, oacc[1][6]);
                    oacc[0][7] = fmaf(p0, v1.w + w01.w, oacc[0][7]); oacc[1][7] = fmaf(p1, v1.w + w11.w, oacc[1][7]);
                }
            }
        }
    }

    // epilogue: out = acc/l + rv0, split to bf16 hi/lo planes
    float4 r0 = *(const float4*)&sm.rv0[kg * 8];
    float4 r1 = *(const float4*)&sm.rv0[kg * 8 + 4];
    #pragma unroll
    for (int r = 0; r < 2; r++) {
        int tr = t0 + lrow0 + r;
        float invl = 1.0f / l_[r];
        float ov[8] = {
            oacc[r][0]*invl + r0.x, oacc[r][1]*invl + r0.y,
            oacc[r][2]*invl + r0.z, oacc[r][3]*invl + r0.w,
            oacc[r][4]*invl + r1.x, oacc[r][5]*invl + r1.y,
            oacc[r][6]*invl + r1.z, oacc[r][7]*invl + r1.w };
        size_t oidx = (size_t)(b * T_ + tr) * NX_ + h * 64 + kg * 8;
        uint32_t hp[4], lp[4];
        #pragma unroll
        for (int q = 0; q < 4; q++) {
            __nv_bfloat162 hh, ll;
            hh.x = __float2bfloat16(ov[q*2]);
            hh.y = __float2bfloat16(ov[q*2+1]);
            ll.x = __float2bfloat16(ov[q*2]   - __bfloat162float(hh.x));
            ll.y = __float2bfloat16(ov[q*2+1] - __bfloat162float(hh.y));
            hp[q] = *(uint32_t*)&hh; lp[q] = *(uint32_t*)&ll;
        }
        *(uint4*)(&g_atts[0][oidx]) = make_uint4(hp[0], hp[1], hp[2], hp[3]);
        *(uint4*)(&g_atts[1][oidx]) = make_uint4(lp[0], lp[1], lp[2], lp[3]);
    }
}

// ---------------- launch ----------------
extern "C" void kernel_launch(void* const* d_in, const int* in_sizes, int n_in,
                              void* d_out, int out_size)
{
    const float* x          = (const float*)d_in[0];
    const int*   rel        = (const int*)  d_in[1];
    const float* tds        = (const float*)d_in[2];
    const float* LR_Q       = (const float*)d_in[3];
    const float* LR_K       = (const float*)d_in[4];
    const int*   LR_map     = (const int*)  d_in[5];
    const float* c_attn_w   = (const float*)d_in[6];
    const float* c_attn_b   = (const float*)d_in[7];
    const float* c_proj_w   = (const float*)d_in[8];
    const float* c_proj_b   = (const float*)d_in[9];
    const float* rel_w_emb  = (const float*)d_in[10];
    const float* rel_k_emb  = (const float*)d_in[11];
    const float* rel_v_emb  = (const float*)d_in[12];
    float* out = (float*)d_out;

    cudaFuncSetAttribute(attn_kernel, cudaFuncAttributeMaxDynamicSharedMemorySize,
                         (int)sizeof(AttSmem));

    __nv_bfloat16 *xs, *w1s, *w2s, *atts;
    cudaGetSymbolAddress((void**)&xs, g_xs);
    cudaGetSymbolAddress((void**)&w1s, g_w1s);
    cudaGetSymbolAddress((void**)&w2s, g_w2s);
    cudaGetSymbolAddress((void**)&atts, g_atts);
    float* qkv_buf; cudaGetSymbolAddress((void**)&qkv_buf, g_qkv);

    const int NXM = B_ * T_ * NX_;        // 4194304
    split_kernel<<<NXM / 1024, 256>>>(x, xs, xs + NXM, NXM / 4);
    split_kernel<<<(NX_*3*NX_) / 1024, 256>>>(c_attn_w, w1s, w1s + NX_*3*NX_, (NX_*3*NX_) / 4);
    split_kernel<<<(NX_*NX_) / 1024, 256>>>(c_proj_w, w2s, w2s + NX_*NX_, (NX_*NX_) / 4);

    gemm_bf16x3s<<<dim3(24, 32), 256>>>(xs, w1s, c_attn_b, qkv_buf, 3072);
    lr2_kernel<<<dim3(16, 64), 256>>>(LR_Q);
    attn_kernel<<<1024, 256, sizeof(AttSmem)>>>(
        rel, tds, LR_K, LR_map, rel_w_emb, rel_k_emb, rel_v_emb);
    gemm_bf16x3s<<<dim3(8, 32), 256>>>(atts, w2s, c_proj_b, out, 1024);
}